// round 5
// baseline (speedup 1.0000x reference)
#include <cuda_runtime.h>
#include <cuda_bf16.h>
#include <cstdint>
#include <math.h>

// ===========================================================================
// VisionAttention (sm_103): bf16-split HMMA GEMMs (128x256 tile, 3-stage
// cp.async pipeline) + fp32 block-diag attention with fused RoPE
// ===========================================================================

#define S_LEN 2048
#define HID   1280
#define NHEAD 16
#define HDIM  80
#define QKV_N (3 * HID)   // 3840
#define SEG   256
#define NSEG  8

// ---------------- device scratch ----------------
__device__ __align__(256) float g_qkv[S_LEN * QKV_N];
__device__ __align__(256) __nv_bfloat16 g_xh[S_LEN * HID];
__device__ __align__(256) __nv_bfloat16 g_xl[S_LEN * HID];
__device__ __align__(256) __nv_bfloat16 g_ah[S_LEN * HID];
__device__ __align__(256) __nv_bfloat16 g_al[S_LEN * HID];
__device__ __align__(256) __nv_bfloat16 g_wqh[QKV_N * HID];  // [N][K]
__device__ __align__(256) __nv_bfloat16 g_wql[QKV_N * HID];
__device__ __align__(256) __nv_bfloat16 g_woh[HID * HID];
__device__ __align__(256) __nv_bfloat16 g_wol[HID * HID];

__device__ __forceinline__ uint32_t smem_to_u32(const void* p) {
    uint32_t a;
    asm("{ .reg .u64 t; cvta.to.shared.u64 t, %1; cvt.u32.u64 %0, t; }"
        : "=r"(a) : "l"(p));
    return a;
}

#define CP_ASYNC16(sa, gp) \
    asm volatile("cp.async.cg.shared.global [%0], [%1], 16;" \
        :: "r"(sa), "l"(gp) : "memory")
#define CP_COMMIT() asm volatile("cp.async.commit_group;" ::: "memory")

#define MMA_BF16(ac, a, b) \
    asm volatile("mma.sync.aligned.m16n8k16.row.col.f32.bf16.bf16.f32 " \
        "{%0,%1,%2,%3},{%4,%5,%6,%7},{%8,%9},{%0,%1,%2,%3};" \
        : "+f"((ac)[0]), "+f"((ac)[1]), "+f"((ac)[2]), "+f"((ac)[3]) \
        : "r"((a)[0]), "r"((a)[1]), "r"((a)[2]), "r"((a)[3]), \
          "r"((b)[0]), "r"((b)[1]))

#define LDSM_X4(r0, r1, r2, r3, addr) \
    asm volatile("ldmatrix.sync.aligned.m8n8.x4.shared.b16 {%0,%1,%2,%3}, [%4];" \
        : "=r"(r0), "=r"(r1), "=r"(r2), "=r"(r3) : "r"(addr))

// ---------------------------------------------------------------------------
// Prep kernels
// ---------------------------------------------------------------------------
__global__ void split_kernel(const float* __restrict__ src,
                             __nv_bfloat16* __restrict__ hi,
                             __nv_bfloat16* __restrict__ lo, int n) {
    int i = blockIdx.x * blockDim.x + threadIdx.x;
    if (i >= n) return;
    float a = src[i];
    __nv_bfloat16 h = __float2bfloat16(a);
    hi[i] = h;
    lo[i] = __float2bfloat16(a - __bfloat162float(h));
}

// W [K][N] fp32 -> Th, Tl [N][K] bf16
__global__ void transpose_split_kernel(const float* __restrict__ W,
                                       __nv_bfloat16* __restrict__ Th,
                                       __nv_bfloat16* __restrict__ Tl,
                                       int K, int N) {
    __shared__ float t[32][33];
    int bn = blockIdx.x, bk = blockIdx.y;
    int tx = threadIdx.x, ty = threadIdx.y;   // 32 x 8
#pragma unroll
    for (int i = 0; i < 4; i++)
        t[ty + i * 8][tx] = W[(size_t)(bk * 32 + ty + i * 8) * N + bn * 32 + tx];
    __syncthreads();
#pragma unroll
    for (int i = 0; i < 4; i++) {
        float a = t[tx][ty + i * 8];
        __nv_bfloat16 h = __float2bfloat16(a);
        size_t o = (size_t)(bn * 32 + ty + i * 8) * K + bk * 32 + tx;
        Th[o] = h;
        Tl[o] = __float2bfloat16(a - __bfloat162float(h));
    }
}

// ---------------------------------------------------------------------------
// bf16-split GEMM (3 products): C[M,N] = (Ah+Al)@(Bh+Bl)^T + bias.
// CTA tile 128x256, warp tile 64x64, BK=32, 3-stage cp.async pipeline.
// smem tiles padded to 80B rows (conflict-free ldmatrix).
// ---------------------------------------------------------------------------
#define GBK      32
#define ROW_B    80
#define A_TILE_B (128 * ROW_B)              // 10240
#define B_TILE_B (256 * ROW_B)              // 20480
#define STAGE_B  (2 * A_TILE_B + 2 * B_TILE_B)  // 61440
#define G_SMEM   (3 * STAGE_B)              // 184320

__global__ __launch_bounds__(256)
void gemm_bf16x3_kernel(int M, int N, int K,
                        const __nv_bfloat16* __restrict__ Ah,
                        const __nv_bfloat16* __restrict__ Al,
                        const __nv_bfloat16* __restrict__ Bh,
                        const __nv_bfloat16* __restrict__ Bl,
                        const float* __restrict__ bias,
                        float* __restrict__ C) {
    extern __shared__ __align__(16) char smem[];
    const uint32_t sbase = smem_to_u32(smem);

    const int tid  = threadIdx.x;
    const int wid  = tid >> 5;
    const int lane = tid & 31;
    const int g    = lane >> 2;
    const int tig  = lane & 3;
    const int wm   = wid & 1;         // warp row: 64 rows
    const int wn   = wid >> 1;        // warp col: 64 cols (0..3)
    const int n0   = blockIdx.x * 256;
    const int m0   = blockIdx.y * 128;

    const __nv_bfloat16* srcA[2] = { Ah + (size_t)m0 * K, Al + (size_t)m0 * K };
    const __nv_bfloat16* srcB[2] = { Bh + (size_t)n0 * K, Bl + (size_t)n0 * K };

    float acc[4][8][4];
#pragma unroll
    for (int i = 0; i < 4; i++)
#pragma unroll
        for (int j = 0; j < 8; j++)
#pragma unroll
            for (int r = 0; r < 4; r++) acc[i][j][r] = 0.f;

    const int KT = K / GBK;   // 40

    // stage copy: A tiles 2x512 chunks, B tiles 2x1024 chunks = 3072 x 16B
    auto issue_stage = [&](int buf, int kt) {
        const uint32_t sb = sbase + buf * STAGE_B;
#pragma unroll
        for (int i = 0; i < 12; i++) {
            const int c = tid + i * 256;
            if (i < 4) {                       // A region: c < 1024
                const int tile = c >> 9, rem = c & 511;
                const int row = rem >> 2, c16 = rem & 3;
                CP_ASYNC16(sb + tile * A_TILE_B + row * ROW_B + c16 * 16,
                           srcA[tile] + (size_t)row * K + kt * GBK + c16 * 8);
            } else {                           // B region
                const int cc = c - 1024;
                const int tile = cc >> 10, rem = cc & 1023;
                const int row = rem >> 2, c16 = rem & 3;
                CP_ASYNC16(sb + 2 * A_TILE_B + tile * B_TILE_B + row * ROW_B + c16 * 16,
                           srcB[tile] + (size_t)row * K + kt * GBK + c16 * 8);
            }
        }
        CP_COMMIT();
    };

    const uint32_t aOff = (uint32_t)(wm * 64 + (lane & 15)) * ROW_B + ((lane >> 4) & 1) * 16;
    const uint32_t bOff = (uint32_t)(wn * 64 + (lane & 15)) * ROW_B + ((lane >> 4) & 1) * 16;

    issue_stage(0, 0);
    issue_stage(1, 1);

    for (int kt = 0; kt < KT; kt++) {
        if (kt + 1 < KT) asm volatile("cp.async.wait_group 1;" ::: "memory");
        else             asm volatile("cp.async.wait_group 0;" ::: "memory");
        __syncthreads();
        if (kt + 2 < KT) issue_stage((kt + 2) % 3, kt + 2);

        const uint32_t stage = sbase + (kt % 3) * STAGE_B;
        const uint32_t aAh = stage + aOff;
        const uint32_t aAl = aAh + A_TILE_B;
        const uint32_t aBh = stage + 2 * A_TILE_B + bOff;
        const uint32_t aBl = aBh + B_TILE_B;

#pragma unroll
        for (int ks = 0; ks < 2; ks++) {
            const uint32_t ko = ks * 32;
            uint32_t ah[4][4], al[4][4];
#pragma unroll
            for (int mt = 0; mt < 4; mt++) {
                LDSM_X4(ah[mt][0], ah[mt][1], ah[mt][2], ah[mt][3],
                        aAh + mt * (16 * ROW_B) + ko);
                LDSM_X4(al[mt][0], al[mt][1], al[mt][2], al[mt][3],
                        aAl + mt * (16 * ROW_B) + ko);
            }
#pragma unroll
            for (int half = 0; half < 2; half++) {
                uint32_t bh[4][2], bl[4][2];
#pragma unroll
                for (int np = 0; np < 2; np++) {
                    const uint32_t ro = (half * 2 + np) * (16 * ROW_B) + ko;
                    LDSM_X4(bh[np*2][0], bh[np*2+1][0], bh[np*2][1], bh[np*2+1][1],
                            aBh + ro);
                    LDSM_X4(bl[np*2][0], bl[np*2+1][0], bl[np*2][1], bl[np*2+1][1],
                            aBl + ro);
                }
#pragma unroll
                for (int mt = 0; mt < 4; mt++)
#pragma unroll
                    for (int nt = 0; nt < 4; nt++) {
                        MMA_BF16(acc[mt][half*4+nt], ah[mt], bh[nt]);
                        MMA_BF16(acc[mt][half*4+nt], ah[mt], bl[nt]);
                        MMA_BF16(acc[mt][half*4+nt], al[mt], bh[nt]);
                    }
            }
        }
        __syncthreads();
    }

    // epilogue
#pragma unroll
    for (int nt = 0; nt < 8; nt++) {
        const int col = n0 + wn * 64 + nt * 8 + tig * 2;
        const float b0 = bias[col], b1 = bias[col + 1];
#pragma unroll
        for (int mt = 0; mt < 4; mt++) {
            const int row0 = m0 + wm * 64 + mt * 16 + g;
            float2 v0 = make_float2(acc[mt][nt][0] + b0, acc[mt][nt][1] + b1);
            float2 v1 = make_float2(acc[mt][nt][2] + b0, acc[mt][nt][3] + b1);
            *(float2*)&C[(size_t)row0 * N + col]       = v0;
            *(float2*)&C[(size_t)(row0 + 8) * N + col] = v1;
        }
    }
}

// ---------------------------------------------------------------------------
// Block-diagonal attention with fused RoPE, float4 smem, bf16-split epilogue.
// grid = (4 qtiles, 8 segs, 16 heads), 256 threads.
// qkv holds RAW q,k (rope applied here in smem).
// ---------------------------------------------------------------------------
#define QT     64
#define SQ_LD  88
#define SS_LD  260
#define ATTN_SMEM ((QT*SQ_LD + SEG*SQ_LD + QT*SS_LD) * 4)

__global__ __launch_bounds__(256, 1)
void attn_kernel(const float* __restrict__ qkv,
                 const float* __restrict__ cosb,
                 const float* __restrict__ sinb,
                 const int* __restrict__ cu,
                 __nv_bfloat16* __restrict__ oh,
                 __nv_bfloat16* __restrict__ ol) {
    extern __shared__ float sm[];
    float* sQ = sm;
    float* sK = sQ + QT * SQ_LD;
    float* sS = sK + SEG * SQ_LD;

    const int tid  = threadIdx.x;
    const int qt   = blockIdx.x;
    const int seg  = blockIdx.y;
    const int head = blockIdx.z;

    const int segStart = cu[seg];
    const int q0 = segStart + qt * QT;
    const float scale = rsqrtf((float)HDIM);

    // raw loads
    for (int i = tid; i < QT * 20; i += 256) {
        int r = i / 20, d4 = i % 20;
        *(float4*)&sQ[r * SQ_LD + d4 * 4] =
            *(const float4*)&qkv[(size_t)(q0 + r) * QKV_N + head * HDIM + d4 * 4];
    }
    for (int i = tid; i < SEG * 20; i += 256) {
        int r = i / 20, d4 = i % 20;
        *(float4*)&sK[r * SQ_LD + d4 * 4] =
            *(const float4*)&qkv[(size_t)(segStart + r) * QKV_N + HID + head * HDIM + d4 * 4];
    }
    __syncthreads();

    // fused RoPE in smem (pairs d, d+40); q gets softmax scale folded in
    for (int i = tid; i < QT * 40; i += 256) {
        int r = i / 40, d = i % 40;
        int s = q0 + r;
        float c1 = cosb[s * HDIM + d],      s1 = sinb[s * HDIM + d];
        float c2 = cosb[s * HDIM + d + 40], s2 = sinb[s * HDIM + d + 40];
        float q1 = sQ[r * SQ_LD + d], q2 = sQ[r * SQ_LD + d + 40];
        sQ[r * SQ_LD + d]      = (q1 * c1 - q2 * s1) * scale;
        sQ[r * SQ_LD + d + 40] = (q2 * c2 + q1 * s2) * scale;
    }
    for (int i = tid; i < SEG * 40; i += 256) {
        int r = i / 40, d = i % 40;
        int s = segStart + r;
        float c1 = cosb[s * HDIM + d],      s1 = sinb[s * HDIM + d];
        float c2 = cosb[s * HDIM + d + 40], s2 = sinb[s * HDIM + d + 40];
        float k1 = sK[r * SQ_LD + d], k2 = sK[r * SQ_LD + d + 40];
        sK[r * SQ_LD + d]      = k1 * c1 - k2 * s1;
        sK[r * SQ_LD + d + 40] = k2 * c2 + k1 * s2;
    }
    __syncthreads();

    const int ti = tid >> 4;
    const int tj = tid & 15;

    // ---- phase 1: scores = Q @ K^T
    {
        float acc[4][16];
#pragma unroll
        for (int a = 0; a < 4; a++)
#pragma unroll
            for (int b = 0; b < 16; b++) acc[a][b] = 0.f;

        for (int d4 = 0; d4 < 20; d4++) {
            float4 qr[4];
#pragma unroll
            for (int a = 0; a < 4; a++)
                qr[a] = *(const float4*)&sQ[(ti * 4 + a) * SQ_LD + d4 * 4];
#pragma unroll
            for (int b = 0; b < 16; b++) {
                float4 kv = *(const float4*)&sK[(tj + 16 * b) * SQ_LD + d4 * 4];
#pragma unroll
                for (int a = 0; a < 4; a++) {
                    acc[a][b] = fmaf(qr[a].x, kv.x, acc[a][b]);
                    acc[a][b] = fmaf(qr[a].y, kv.y, acc[a][b]);
                    acc[a][b] = fmaf(qr[a].z, kv.z, acc[a][b]);
                    acc[a][b] = fmaf(qr[a].w, kv.w, acc[a][b]);
                }
            }
        }
#pragma unroll
        for (int a = 0; a < 4; a++)
#pragma unroll
            for (int b = 0; b < 16; b++)
                sS[(ti * 4 + a) * SS_LD + tj + 16 * b] = acc[a][b];
    }
    __syncthreads();

    // reload V into K buffer
    for (int i = tid; i < SEG * 20; i += 256) {
        int r = i / 20, d4 = i % 20;
        *(float4*)&sK[r * SQ_LD + d4 * 4] =
            *(const float4*)&qkv[(size_t)(segStart + r) * QKV_N + 2 * HID + head * HDIM + d4 * 4];
    }

    // ---- softmax
    {
        const int r  = tid >> 2;
        const int cl = tid & 3;
        float mx = -1e30f;
#pragma unroll
        for (int j = 0; j < 64; j++)
            mx = fmaxf(mx, sS[r * SS_LD + cl + 4 * j]);
        mx = fmaxf(mx, __shfl_xor_sync(0xFFFFFFFFu, mx, 1));
        mx = fmaxf(mx, __shfl_xor_sync(0xFFFFFFFFu, mx, 2));
        float sum = 0.f;
#pragma unroll
        for (int j = 0; j < 64; j++) {
            int c = cl + 4 * j;
            float e = __expf(sS[r * SS_LD + c] - mx);
            sS[r * SS_LD + c] = e;
            sum += e;
        }
        sum += __shfl_xor_sync(0xFFFFFFFFu, sum, 1);
        sum += __shfl_xor_sync(0xFFFFFFFFu, sum, 2);
        float inv = 1.f / sum;
#pragma unroll
        for (int j = 0; j < 64; j++) sS[r * SS_LD + cl + 4 * j] *= inv;
    }
    __syncthreads();

    // ---- phase 2: out = P @ V, bf16-split epilogue
    {
        float acc[4][5];
#pragma unroll
        for (int a = 0; a < 4; a++)
#pragma unroll
            for (int u = 0; u < 5; u++) acc[a][u] = 0.f;

        for (int c4 = 0; c4 < 64; c4++) {
            float4 wv[4];
#pragma unroll
            for (int a = 0; a < 4; a++)
                wv[a] = *(const float4*)&sS[(ti * 4 + a) * SS_LD + c4 * 4];
#pragma unroll
            for (int cc = 0; cc < 4; cc++) {
                const int c = c4 * 4 + cc;
                float vr[5];
#pragma unroll
                for (int u = 0; u < 5; u++) vr[u] = sK[c * SQ_LD + tj + 16 * u];
                const float w0 = (cc == 0) ? wv[0].x : (cc == 1) ? wv[0].y : (cc == 2) ? wv[0].z : wv[0].w;
                const float w1 = (cc == 0) ? wv[1].x : (cc == 1) ? wv[1].y : (cc == 2) ? wv[1].z : wv[1].w;
                const float w2 = (cc == 0) ? wv[2].x : (cc == 1) ? wv[2].y : (cc == 2) ? wv[2].z : wv[2].w;
                const float w3 = (cc == 0) ? wv[3].x : (cc == 1) ? wv[3].y : (cc == 2) ? wv[3].z : wv[3].w;
#pragma unroll
                for (int u = 0; u < 5; u++) {
                    acc[0][u] = fmaf(w0, vr[u], acc[0][u]);
                    acc[1][u] = fmaf(w1, vr[u], acc[1][u]);
                    acc[2][u] = fmaf(w2, vr[u], acc[2][u]);
                    acc[3][u] = fmaf(w3, vr[u], acc[3][u]);
                }
            }
        }
#pragma unroll
        for (int a = 0; a < 4; a++) {
            const int row = q0 + ti * 4 + a;
#pragma unroll
            for (int u = 0; u < 5; u++) {
                const int d = tj + 16 * u;
                const size_t o = (size_t)row * HID + head * HDIM + d;
                float v = acc[a][u];
                __nv_bfloat16 h = __float2bfloat16(v);
                oh[o] = h;
                ol[o] = __float2bfloat16(v - __bfloat162float(h));
            }
        }
    }
}

// ---------------------------------------------------------------------------
extern "C" void kernel_launch(void* const* d_in, const int* in_sizes, int n_in,
                              void* d_out, int out_size) {
    const float* x      = (const float*)d_in[0];
    const float* cosb   = (const float*)d_in[1];
    const float* sinb   = (const float*)d_in[2];
    const float* W_qkv  = (const float*)d_in[3];
    const float* b_qkv  = (const float*)d_in[4];
    const float* W_out  = (const float*)d_in[5];
    const float* b_out  = (const float*)d_in[6];
    const int*   cu     = (const int*)d_in[7];
    float*       outp   = (float*)d_out;

    float* qkv;
    __nv_bfloat16 *xh, *xl, *ah, *al, *wqh, *wql, *woh, *wol;
    cudaGetSymbolAddress((void**)&qkv,  g_qkv);
    cudaGetSymbolAddress((void**)&xh,   g_xh);
    cudaGetSymbolAddress((void**)&xl,   g_xl);
    cudaGetSymbolAddress((void**)&ah,   g_ah);
    cudaGetSymbolAddress((void**)&al,   g_al);
    cudaGetSymbolAddress((void**)&wqh,  g_wqh);
    cudaGetSymbolAddress((void**)&wql,  g_wql);
    cudaGetSymbolAddress((void**)&woh,  g_woh);
    cudaGetSymbolAddress((void**)&wol,  g_wol);

    static bool attr_set = false;
    if (!attr_set) {
        cudaFuncSetAttribute(attn_kernel,
                             cudaFuncAttributeMaxDynamicSharedMemorySize, ATTN_SMEM);
        cudaFuncSetAttribute(gemm_bf16x3_kernel,
                             cudaFuncAttributeMaxDynamicSharedMemorySize, G_SMEM);
        attr_set = true;
    }

    // 0. prep
    {
        int n = S_LEN * HID;
        split_kernel<<<(n + 255) / 256, 256>>>(x, xh, xl, n);
        dim3 tb(32, 8);
        transpose_split_kernel<<<dim3(QKV_N / 32, HID / 32), tb>>>(W_qkv, wqh, wql, HID, QKV_N);
        transpose_split_kernel<<<dim3(HID / 32, HID / 32), tb>>>(W_out, woh, wol, HID, HID);
    }
    // 1. QKV projection (raw q,k; rope happens in attention)
    gemm_bf16x3_kernel<<<dim3(QKV_N / 256, S_LEN / 128), 256, G_SMEM>>>(
        S_LEN, QKV_N, HID, xh, xl, wqh, wql, b_qkv, qkv);
    // 2. attention (fused rope, writes bf16 hi/lo)
    attn_kernel<<<dim3(SEG / QT, NSEG, NHEAD), 256, ATTN_SMEM>>>(
        qkv, cosb, sinb, cu, ah, al);
    // 3. out projection
    gemm_bf16x3_kernel<<<dim3(HID / 256, S_LEN / 128), 256, G_SMEM>>>(
        S_LEN, HID, HID, ah, al, woh, wol, b_out, outp);
}

// round 6
// speedup vs baseline: 1.2025x; 1.2025x over previous
#include <cuda_runtime.h>
#include <cuda_bf16.h>
#include <cstdint>
#include <math.h>

// ===========================================================================
// VisionAttention (sm_103): bf16-split HMMA for BOTH projections and
// block-diagonal attention. fp32 softmax.
// ===========================================================================

#define S_LEN 2048
#define HID   1280
#define NHEAD 16
#define HDIM  80
#define QKV_N (3 * HID)   // 3840
#define SEG   256
#define NSEG  8

// ---------------- device scratch ----------------
__device__ __align__(256) float g_qkv[S_LEN * QKV_N];
__device__ __align__(256) __nv_bfloat16 g_xh[S_LEN * HID];
__device__ __align__(256) __nv_bfloat16 g_xl[S_LEN * HID];
__device__ __align__(256) __nv_bfloat16 g_ah[S_LEN * HID];
__device__ __align__(256) __nv_bfloat16 g_al[S_LEN * HID];
__device__ __align__(256) __nv_bfloat16 g_wqh[QKV_N * HID];
__device__ __align__(256) __nv_bfloat16 g_wql[QKV_N * HID];
__device__ __align__(256) __nv_bfloat16 g_woh[HID * HID];
__device__ __align__(256) __nv_bfloat16 g_wol[HID * HID];
// rope-applied, bf16-split q/k and split v, layout [s][h*80+d]
__device__ __align__(256) __nv_bfloat16 g_qh[S_LEN * HID];
__device__ __align__(256) __nv_bfloat16 g_ql[S_LEN * HID];
__device__ __align__(256) __nv_bfloat16 g_kh[S_LEN * HID];
__device__ __align__(256) __nv_bfloat16 g_kl[S_LEN * HID];
__device__ __align__(256) __nv_bfloat16 g_vh[S_LEN * HID];
__device__ __align__(256) __nv_bfloat16 g_vl[S_LEN * HID];

__device__ __forceinline__ uint32_t smem_to_u32(const void* p) {
    uint32_t a;
    asm("{ .reg .u64 t; cvta.to.shared.u64 t, %1; cvt.u32.u64 %0, t; }"
        : "=r"(a) : "l"(p));
    return a;
}

#define CP_ASYNC16(sa, gp) \
    asm volatile("cp.async.cg.shared.global [%0], [%1], 16;" \
        :: "r"(sa), "l"(gp) : "memory")
#define CP_COMMIT() asm volatile("cp.async.commit_group;" ::: "memory")

#define MMA_BF16(ac, a, b) \
    asm volatile("mma.sync.aligned.m16n8k16.row.col.f32.bf16.bf16.f32 " \
        "{%0,%1,%2,%3},{%4,%5,%6,%7},{%8,%9},{%0,%1,%2,%3};" \
        : "+f"((ac)[0]), "+f"((ac)[1]), "+f"((ac)[2]), "+f"((ac)[3]) \
        : "r"((a)[0]), "r"((a)[1]), "r"((a)[2]), "r"((a)[3]), \
          "r"((b)[0]), "r"((b)[1]))

#define LDSM_X4(r0, r1, r2, r3, addr) \
    asm volatile("ldmatrix.sync.aligned.m8n8.x4.shared.b16 {%0,%1,%2,%3}, [%4];" \
        : "=r"(r0), "=r"(r1), "=r"(r2), "=r"(r3) : "r"(addr))
#define LDSM_X4T(r0, r1, r2, r3, addr) \
    asm volatile("ldmatrix.sync.aligned.m8n8.x4.trans.shared.b16 {%0,%1,%2,%3}, [%4];" \
        : "=r"(r0), "=r"(r1), "=r"(r2), "=r"(r3) : "r"(addr))
#define LDSM_X2T(r0, r1, addr) \
    asm volatile("ldmatrix.sync.aligned.m8n8.x2.trans.shared.b16 {%0,%1}, [%2];" \
        : "=r"(r0), "=r"(r1) : "r"(addr))

// split a float2 into packed-bf16 hi and lo parts (low half = .x)
__device__ __forceinline__ void split2(float2 p, uint32_t& hi, uint32_t& lo) {
    __nv_bfloat16 hx = __float2bfloat16(p.x);
    __nv_bfloat16 hy = __float2bfloat16(p.y);
    float lx = p.x - __bfloat162float(hx);
    float ly = p.y - __bfloat162float(hy);
    __nv_bfloat16 lxb = __float2bfloat16(lx);
    __nv_bfloat16 lyb = __float2bfloat16(ly);
    hi = (uint32_t)__bfloat16_as_ushort(hx) | ((uint32_t)__bfloat16_as_ushort(hy) << 16);
    lo = (uint32_t)__bfloat16_as_ushort(lxb) | ((uint32_t)__bfloat16_as_ushort(lyb) << 16);
}

// ---------------------------------------------------------------------------
// Prep kernels
// ---------------------------------------------------------------------------
__global__ void split_kernel(const float* __restrict__ src,
                             __nv_bfloat16* __restrict__ hi,
                             __nv_bfloat16* __restrict__ lo, int n) {
    int i = blockIdx.x * blockDim.x + threadIdx.x;
    if (i >= n) return;
    float a = src[i];
    __nv_bfloat16 h = __float2bfloat16(a);
    hi[i] = h;
    lo[i] = __float2bfloat16(a - __bfloat162float(h));
}

// W [K][N] fp32 -> Th, Tl [N][K] bf16
__global__ void transpose_split_kernel(const float* __restrict__ W,
                                       __nv_bfloat16* __restrict__ Th,
                                       __nv_bfloat16* __restrict__ Tl,
                                       int K, int N) {
    __shared__ float t[32][33];
    int bn = blockIdx.x, bk = blockIdx.y;
    int tx = threadIdx.x, ty = threadIdx.y;
#pragma unroll
    for (int i = 0; i < 4; i++)
        t[ty + i * 8][tx] = W[(size_t)(bk * 32 + ty + i * 8) * N + bn * 32 + tx];
    __syncthreads();
#pragma unroll
    for (int i = 0; i < 4; i++) {
        float a = t[tx][ty + i * 8];
        __nv_bfloat16 h = __float2bfloat16(a);
        size_t o = (size_t)(bn * 32 + ty + i * 8) * K + bk * 32 + tx;
        Th[o] = h;
        Tl[o] = __float2bfloat16(a - __bfloat162float(h));
    }
}

// rope + split q,k: qkv fp32 -> qh/ql/kh/kl bf16 (q gets softmax scale)
__global__ void rope_split_kernel(const float* __restrict__ qkv,
                                  const float* __restrict__ cosb,
                                  const float* __restrict__ sinb,
                                  __nv_bfloat16* __restrict__ qh,
                                  __nv_bfloat16* __restrict__ ql,
                                  __nv_bfloat16* __restrict__ kh,
                                  __nv_bfloat16* __restrict__ kl) {
    int idx = blockIdx.x * blockDim.x + threadIdx.x;
    const int total = S_LEN * NHEAD * 40;
    if (idx >= total) return;
    int s   = idx / (NHEAD * 40);
    int rem = idx % (NHEAD * 40);
    int h   = rem / 40;
    int d   = rem % 40;
    const float scale = rsqrtf((float)HDIM);

    float c1 = cosb[s * HDIM + d],      s1 = sinb[s * HDIM + d];
    float c2 = cosb[s * HDIM + d + 40], s2 = sinb[s * HDIM + d + 40];

    size_t gb = (size_t)s * QKV_N + h * HDIM + d;
    size_t ob = (size_t)s * HID + h * HDIM + d;

    float q1 = qkv[gb], q2 = qkv[gb + 40];
    float qa = (q1 * c1 - q2 * s1) * scale;
    float qb = (q2 * c2 + q1 * s2) * scale;
    float k1 = qkv[gb + HID], k2 = qkv[gb + HID + 40];
    float ka = k1 * c1 - k2 * s1;
    float kb = k2 * c2 + k1 * s2;

    __nv_bfloat16 t;
    t = __float2bfloat16(qa); qh[ob] = t;      ql[ob]      = __float2bfloat16(qa - __bfloat162float(t));
    t = __float2bfloat16(qb); qh[ob + 40] = t; ql[ob + 40] = __float2bfloat16(qb - __bfloat162float(t));
    t = __float2bfloat16(ka); kh[ob] = t;      kl[ob]      = __float2bfloat16(ka - __bfloat162float(t));
    t = __float2bfloat16(kb); kh[ob + 40] = t; kl[ob + 40] = __float2bfloat16(kb - __bfloat162float(t));
}

// split v third of qkv
__global__ void vsplit_kernel(const float* __restrict__ qkv,
                              __nv_bfloat16* __restrict__ vh,
                              __nv_bfloat16* __restrict__ vl) {
    int idx = blockIdx.x * blockDim.x + threadIdx.x;
    if (idx >= S_LEN * HID) return;
    int s = idx / HID, j = idx % HID;
    float v = qkv[(size_t)s * QKV_N + 2 * HID + j];
    __nv_bfloat16 h = __float2bfloat16(v);
    vh[idx] = h;
    vl[idx] = __float2bfloat16(v - __bfloat162float(h));
}

// ---------------------------------------------------------------------------
// bf16-split GEMM (R4 config): 128x128 tile, BK=32, 2-stage, 2 CTA/SM.
// ---------------------------------------------------------------------------
#define GBK        32
#define ROW_B      80
#define TILE_B     (128 * ROW_B)
#define STAGE_B    (4 * TILE_B)
#define G_SMEM     (2 * STAGE_B)

__global__ __launch_bounds__(256, 2)
void gemm_bf16x3_kernel(int M, int N, int K,
                        const __nv_bfloat16* __restrict__ Ah,
                        const __nv_bfloat16* __restrict__ Al,
                        const __nv_bfloat16* __restrict__ Bh,
                        const __nv_bfloat16* __restrict__ Bl,
                        const float* __restrict__ bias,
                        float* __restrict__ C) {
    extern __shared__ __align__(16) char smem[];
    const uint32_t sbase = smem_to_u32(smem);

    const int tid  = threadIdx.x;
    const int wid  = tid >> 5;
    const int lane = tid & 31;
    const int g    = lane >> 2;
    const int tig  = lane & 3;
    const int wm   = wid & 1;
    const int wn   = wid >> 1;
    const int n0   = blockIdx.x * 128;
    const int m0   = blockIdx.y * 128;

    const __nv_bfloat16* srcs[4] = {
        Ah + (size_t)m0 * K, Al + (size_t)m0 * K,
        Bh + (size_t)n0 * K, Bl + (size_t)n0 * K };

    float acc[4][4][4];
#pragma unroll
    for (int i = 0; i < 4; i++)
#pragma unroll
        for (int j = 0; j < 4; j++)
#pragma unroll
            for (int r = 0; r < 4; r++) acc[i][j][r] = 0.f;

    const int KT = K / GBK;

    auto issue_stage = [&](int buf, int kt) {
#pragma unroll
        for (int i = 0; i < 8; i++) {
            int c    = tid + i * 256;
            int tile = c >> 9;
            int rem  = c & 511;
            int row  = rem >> 2;
            int c16  = rem & 3;
            const __nv_bfloat16* gp = srcs[tile] + (size_t)row * K + kt * GBK + c16 * 8;
            uint32_t sa = sbase + buf * STAGE_B + tile * TILE_B + row * ROW_B + c16 * 16;
            CP_ASYNC16(sa, gp);
        }
        CP_COMMIT();
    };

    const uint32_t aOff = (uint32_t)(wm * 64 + (lane & 15)) * ROW_B + ((lane >> 4) & 1) * 16;
    const uint32_t bOff = (uint32_t)(wn * 32 + (lane & 15)) * ROW_B + ((lane >> 4) & 1) * 16;

    issue_stage(0, 0);

    for (int kt = 0; kt < KT; kt++) {
        const int buf = kt & 1;
        if (kt + 1 < KT) {
            issue_stage(buf ^ 1, kt + 1);
            asm volatile("cp.async.wait_group 1;" ::: "memory");
        } else {
            asm volatile("cp.async.wait_group 0;" ::: "memory");
        }
        __syncthreads();

        const uint32_t stage = sbase + buf * STAGE_B;
        const uint32_t aAh = stage + aOff;
        const uint32_t aAl = aAh + TILE_B;
        const uint32_t aBh = stage + 2 * TILE_B + bOff;
        const uint32_t aBl = aBh + TILE_B;

#pragma unroll
        for (int ks = 0; ks < 2; ks++) {
            const uint32_t ko = ks * 32;
            uint32_t bh[4][2], bl[4][2];
#pragma unroll
            for (int np = 0; np < 2; np++) {
                LDSM_X4(bh[np*2][0], bh[np*2+1][0], bh[np*2][1], bh[np*2+1][1],
                        aBh + np * (16 * ROW_B) + ko);
                LDSM_X4(bl[np*2][0], bl[np*2+1][0], bl[np*2][1], bl[np*2+1][1],
                        aBl + np * (16 * ROW_B) + ko);
            }
            uint32_t ah[4][4], al[4][4];
#pragma unroll
            for (int mt = 0; mt < 4; mt++) {
                LDSM_X4(ah[mt][0], ah[mt][1], ah[mt][2], ah[mt][3],
                        aAh + mt * (16 * ROW_B) + ko);
                LDSM_X4(al[mt][0], al[mt][1], al[mt][2], al[mt][3],
                        aAl + mt * (16 * ROW_B) + ko);
            }
#pragma unroll
            for (int mt = 0; mt < 4; mt++)
#pragma unroll
                for (int nt = 0; nt < 4; nt++) {
                    MMA_BF16(acc[mt][nt], ah[mt], bh[nt]);
                    MMA_BF16(acc[mt][nt], ah[mt], bl[nt]);
                    MMA_BF16(acc[mt][nt], al[mt], bh[nt]);
                }
        }
        __syncthreads();
    }

#pragma unroll
    for (int mt = 0; mt < 4; mt++) {
        const int row0 = m0 + wm * 64 + mt * 16 + g;
#pragma unroll
        for (int nt = 0; nt < 4; nt++) {
            const int col = n0 + wn * 32 + nt * 8 + tig * 2;
            const float b0 = bias[col], b1 = bias[col + 1];
            float2 v0 = make_float2(acc[mt][nt][0] + b0, acc[mt][nt][1] + b1);
            float2 v1 = make_float2(acc[mt][nt][2] + b0, acc[mt][nt][3] + b1);
            *(float2*)&C[(size_t)row0 * N + col]       = v0;
            *(float2*)&C[(size_t)(row0 + 8) * N + col] = v1;
        }
    }
}

// ---------------------------------------------------------------------------
// HMMA block-diagonal attention. grid = (4 qtiles, 8 segs, 16 heads), 256 thr.
// QK^T and PV on tensor pipe (bf16 3-product), fp32 softmax in smem.
// ---------------------------------------------------------------------------
#define AQROW   176                       // bytes per 80-col bf16 smem row
#define ASS_LD  268                       // fp32 score row stride (words)
#define SM_QH   0
#define SM_QL   11264
#define SM_KH   22528                     // 256*176 = 45056; reused for V
#define SM_KL   67584
#define SM_SS   112640
#define ATTN_SMEM (112640 + 64 * ASS_LD * 4)   // 181248

__global__ __launch_bounds__(256, 1)
void attn_mma_kernel(const __nv_bfloat16* __restrict__ qh_g,
                     const __nv_bfloat16* __restrict__ ql_g,
                     const __nv_bfloat16* __restrict__ kh_g,
                     const __nv_bfloat16* __restrict__ kl_g,
                     const __nv_bfloat16* __restrict__ vh_g,
                     const __nv_bfloat16* __restrict__ vl_g,
                     const int* __restrict__ cu,
                     __nv_bfloat16* __restrict__ oh,
                     __nv_bfloat16* __restrict__ ol) {
    extern __shared__ __align__(16) char sm[];
    const uint32_t sb = smem_to_u32(sm);
    float* sS = (float*)(sm + SM_SS);

    const int tid  = threadIdx.x;
    const int wid  = tid >> 5;
    const int lane = tid & 31;
    const int qt   = blockIdx.x;
    const int seg  = blockIdx.y;
    const int head = blockIdx.z;

    const int segStart = cu[seg];
    const int q0 = segStart + qt * 64;
    const int hb = head * HDIM;

    // ---- load q (64x80) and k (256x80) hi/lo tiles
    for (int i = tid; i < 640; i += 256) {
        int r = i / 10, c = i % 10;
        const size_t go = (size_t)(q0 + r) * HID + hb + c * 8;
        *(uint4*)(sm + SM_QH + r * AQROW + c * 16) = *(const uint4*)(qh_g + go);
        *(uint4*)(sm + SM_QL + r * AQROW + c * 16) = *(const uint4*)(ql_g + go);
    }
    for (int i = tid; i < 2560; i += 256) {
        int r = i / 10, c = i % 10;
        const size_t go = (size_t)(segStart + r) * HID + hb + c * 8;
        *(uint4*)(sm + SM_KH + r * AQROW + c * 16) = *(const uint4*)(kh_g + go);
        *(uint4*)(sm + SM_KL + r * AQROW + c * 16) = *(const uint4*)(kl_g + go);
    }
    __syncthreads();

    // ---- QK^T: warp grid 2(m) x 4(n); warp tile 32 x 64
    {
        const int wm = wid & 1, wn = wid >> 1;
        float acc[2][8][4];
#pragma unroll
        for (int i = 0; i < 2; i++)
#pragma unroll
            for (int j = 0; j < 8; j++)
#pragma unroll
                for (int r = 0; r < 4; r++) acc[i][j][r] = 0.f;

        const uint32_t aBase = sb + SM_QH + (uint32_t)(wm * 32 + (lane & 15)) * AQROW
                               + ((lane >> 4) & 1) * 16;
        const uint32_t bBase = sb + SM_KH + (uint32_t)(wn * 64 + (lane & 15)) * AQROW
                               + ((lane >> 4) & 1) * 16;

#pragma unroll
        for (int ks = 0; ks < 5; ks++) {
            const uint32_t ko = ks * 32;
            uint32_t ah[2][4], al[2][4];
#pragma unroll
            for (int mt = 0; mt < 2; mt++) {
                LDSM_X4(ah[mt][0], ah[mt][1], ah[mt][2], ah[mt][3],
                        aBase + mt * (16 * AQROW) + ko);
                LDSM_X4(al[mt][0], al[mt][1], al[mt][2], al[mt][3],
                        aBase + (SM_QL - SM_QH) + mt * (16 * AQROW) + ko);
            }
#pragma unroll
            for (int np = 0; np < 4; np++) {
                uint32_t bh[2][2], bl[2][2];
                LDSM_X4(bh[0][0], bh[1][0], bh[0][1], bh[1][1],
                        bBase + np * (16 * AQROW) + ko);
                LDSM_X4(bl[0][0], bl[1][0], bl[0][1], bl[1][1],
                        bBase + (SM_KL - SM_KH) + np * (16 * AQROW) + ko);
#pragma unroll
                for (int mt = 0; mt < 2; mt++)
#pragma unroll
                    for (int j = 0; j < 2; j++) {
                        MMA_BF16(acc[mt][np*2+j], ah[mt], bh[j]);
                        MMA_BF16(acc[mt][np*2+j], ah[mt], bl[j]);
                        MMA_BF16(acc[mt][np*2+j], al[mt], bh[j]);
                    }
            }
        }
        // write scores fp32
#pragma unroll
        for (int mt = 0; mt < 2; mt++) {
            const int r = wm * 32 + mt * 16 + (lane >> 2);
#pragma unroll
            for (int nt = 0; nt < 8; nt++) {
                const int c = wn * 64 + nt * 8 + 2 * (lane & 3);
                *(float2*)&sS[r * ASS_LD + c] =
                    make_float2(acc[mt][nt][0], acc[mt][nt][1]);
                *(float2*)&sS[(r + 8) * ASS_LD + c] =
                    make_float2(acc[mt][nt][2], acc[mt][nt][3]);
            }
        }
    }
    __syncthreads();

    // ---- load V (overlay K buffers) + softmax
    for (int i = tid; i < 2560; i += 256) {
        int r = i / 10, c = i % 10;
        const size_t go = (size_t)(segStart + r) * HID + hb + c * 8;
        *(uint4*)(sm + SM_KH + r * AQROW + c * 16) = *(const uint4*)(vh_g + go);
        *(uint4*)(sm + SM_KL + r * AQROW + c * 16) = *(const uint4*)(vl_g + go);
    }
    {
        const int r  = tid >> 2;
        const int cl = tid & 3;
        float mx = -1e30f;
#pragma unroll
        for (int j = 0; j < 64; j++)
            mx = fmaxf(mx, sS[r * ASS_LD + cl + 4 * j]);
        mx = fmaxf(mx, __shfl_xor_sync(0xFFFFFFFFu, mx, 1));
        mx = fmaxf(mx, __shfl_xor_sync(0xFFFFFFFFu, mx, 2));
        float sum = 0.f;
#pragma unroll
        for (int j = 0; j < 64; j++) {
            int c = cl + 4 * j;
            float e = __expf(sS[r * ASS_LD + c] - mx);
            sS[r * ASS_LD + c] = e;
            sum += e;
        }
        sum += __shfl_xor_sync(0xFFFFFFFFu, sum, 1);
        sum += __shfl_xor_sync(0xFFFFFFFFu, sum, 2);
        float inv = 1.f / sum;
#pragma unroll
        for (int j = 0; j < 64; j++) sS[r * ASS_LD + cl + 4 * j] *= inv;
    }
    __syncthreads();

    // ---- PV: warp grid 4(m) x 2(n); warp tile 16 rows x 40 d-cols
    {
        const int wr = wid >> 1, wc = wid & 1;
        float facc[5][4];
#pragma unroll
        for (int i = 0; i < 5; i++)
#pragma unroll
            for (int r = 0; r < 4; r++) facc[i][r] = 0.f;

        const int pr = wr * 16 + (lane >> 2);
        const uint32_t vRowOff = (uint32_t)((lane & 7) + ((lane >> 3) & 1) * 8) * AQROW;
        const uint32_t vColHi  = ((lane >> 4) & 1) * 16;   // +8 cols (bf16)

#pragma unroll
        for (int ks = 0; ks < 16; ks++) {
            const int c = ks * 16 + 2 * (lane & 3);
            float2 p00 = *(float2*)&sS[pr * ASS_LD + c];
            float2 p01 = *(float2*)&sS[pr * ASS_LD + c + 8];
            float2 p10 = *(float2*)&sS[(pr + 8) * ASS_LD + c];
            float2 p11 = *(float2*)&sS[(pr + 8) * ASS_LD + c + 8];
            uint32_t pha[4], pla[4];
            split2(p00, pha[0], pla[0]);
            split2(p10, pha[1], pla[1]);
            split2(p01, pha[2], pla[2]);
            split2(p11, pha[3], pla[3]);

            const uint32_t vk = sb + SM_KH + (uint32_t)(ks * 16) * AQROW + vRowOff;

#pragma unroll
            for (int np = 0; np < 2; np++) {
                const uint32_t co = (uint32_t)(wc * 40 + np * 16) * 2 + vColHi;
                uint32_t bh[2][2], bl[2][2];
                LDSM_X4T(bh[0][0], bh[0][1], bh[1][0], bh[1][1], vk + co);
                LDSM_X4T(bl[0][0], bl[0][1], bl[1][0], bl[1][1],
                         vk + (SM_KL - SM_KH) + co);
#pragma unroll
                for (int j = 0; j < 2; j++) {
                    MMA_BF16(facc[np*2+j], pha, bh[j]);
                    MMA_BF16(facc[np*2+j], pha, bl[j]);
                    MMA_BF16(facc[np*2+j], pla, bh[j]);
                }
            }
            {   // nt = 4 via x2.trans
                const uint32_t co = (uint32_t)(wc * 40 + 32) * 2;
                uint32_t b4h[2], b4l[2];
                LDSM_X2T(b4h[0], b4h[1], vk + co);
                LDSM_X2T(b4l[0], b4l[1], vk + (SM_KL - SM_KH) + co);
                MMA_BF16(facc[4], pha, b4h);
                MMA_BF16(facc[4], pha, b4l);
                MMA_BF16(facc[4], pla, b4h);
            }
        }

        // epilogue: bf16 hi/lo split to ah/al
        const int row0 = q0 + wr * 16 + (lane >> 2);
#pragma unroll
        for (int nt = 0; nt < 5; nt++) {
            const int col = hb + wc * 40 + nt * 8 + 2 * (lane & 3);
            uint32_t h0, l0, h1, l1;
            split2(make_float2(facc[nt][0], facc[nt][1]), h0, l0);
            split2(make_float2(facc[nt][2], facc[nt][3]), h1, l1);
            *(uint32_t*)(oh + (size_t)row0 * HID + col)       = h0;
            *(uint32_t*)(ol + (size_t)row0 * HID + col)       = l0;
            *(uint32_t*)(oh + (size_t)(row0 + 8) * HID + col) = h1;
            *(uint32_t*)(ol + (size_t)(row0 + 8) * HID + col) = l1;
        }
    }
}

// ---------------------------------------------------------------------------
extern "C" void kernel_launch(void* const* d_in, const int* in_sizes, int n_in,
                              void* d_out, int out_size) {
    const float* x      = (const float*)d_in[0];
    const float* cosb   = (const float*)d_in[1];
    const float* sinb   = (const float*)d_in[2];
    const float* W_qkv  = (const float*)d_in[3];
    const float* b_qkv  = (const float*)d_in[4];
    const float* W_out  = (const float*)d_in[5];
    const float* b_out  = (const float*)d_in[6];
    const int*   cu     = (const int*)d_in[7];
    float*       outp   = (float*)d_out;

    float* qkv;
    __nv_bfloat16 *xh, *xl, *ah, *al, *wqh, *wql, *woh, *wol;
    __nv_bfloat16 *qh, *ql, *kh, *kl, *vh, *vl;
    cudaGetSymbolAddress((void**)&qkv,  g_qkv);
    cudaGetSymbolAddress((void**)&xh,   g_xh);
    cudaGetSymbolAddress((void**)&xl,   g_xl);
    cudaGetSymbolAddress((void**)&ah,   g_ah);
    cudaGetSymbolAddress((void**)&al,   g_al);
    cudaGetSymbolAddress((void**)&wqh,  g_wqh);
    cudaGetSymbolAddress((void**)&wql,  g_wql);
    cudaGetSymbolAddress((void**)&woh,  g_woh);
    cudaGetSymbolAddress((void**)&wol,  g_wol);
    cudaGetSymbolAddress((void**)&qh,   g_qh);
    cudaGetSymbolAddress((void**)&ql,   g_ql);
    cudaGetSymbolAddress((void**)&kh,   g_kh);
    cudaGetSymbolAddress((void**)&kl,   g_kl);
    cudaGetSymbolAddress((void**)&vh,   g_vh);
    cudaGetSymbolAddress((void**)&vl,   g_vl);

    static bool attr_set = false;
    if (!attr_set) {
        cudaFuncSetAttribute(attn_mma_kernel,
                             cudaFuncAttributeMaxDynamicSharedMemorySize, ATTN_SMEM);
        cudaFuncSetAttribute(gemm_bf16x3_kernel,
                             cudaFuncAttributeMaxDynamicSharedMemorySize, G_SMEM);
        attr_set = true;
    }

    // 0. prep
    {
        int n = S_LEN * HID;
        split_kernel<<<(n + 255) / 256, 256>>>(x, xh, xl, n);
        dim3 tb(32, 8);
        transpose_split_kernel<<<dim3(QKV_N / 32, HID / 32), tb>>>(W_qkv, wqh, wql, HID, QKV_N);
        transpose_split_kernel<<<dim3(HID / 32, HID / 32), tb>>>(W_out, woh, wol, HID, HID);
    }
    // 1. QKV projection
    gemm_bf16x3_kernel<<<dim3(QKV_N / 128, S_LEN / 128), 256, G_SMEM>>>(
        S_LEN, QKV_N, HID, xh, xl, wqh, wql, b_qkv, qkv);
    // 2. rope + split q,k ; split v
    {
        int t1 = S_LEN * NHEAD * 40;
        rope_split_kernel<<<(t1 + 255) / 256, 256>>>(qkv, cosb, sinb, qh, ql, kh, kl);
        int t2 = S_LEN * HID;
        vsplit_kernel<<<(t2 + 255) / 256, 256>>>(qkv, vh, vl);
    }
    // 3. HMMA attention -> ah/al
    attn_mma_kernel<<<dim3(4, NSEG, NHEAD), 256, ATTN_SMEM>>>(
        qh, ql, kh, kl, vh, vl, cu, ah, al);
    // 4. out projection
    gemm_bf16x3_kernel<<<dim3(HID / 128, S_LEN / 128), 256, G_SMEM>>>(
        S_LEN, HID, HID, ah, al, woh, wol, b_out, outp);
}

// round 7
// speedup vs baseline: 1.5921x; 1.3240x over previous
#include <cuda_runtime.h>
#include <cuda_fp16.h>
#include <cuda_bf16.h>
#include <cstdint>
#include <math.h>

// ===========================================================================
// VisionAttention (sm_103): fp16 2-product HMMA GEMMs + HMMA attention
// A = Ah+Al (fp16 split), B = fp16 rounded. Error ~2^-12 ≈ 1.5e-4.
// ===========================================================================

#define S_LEN 2048
#define HID   1280
#define NHEAD 16
#define HDIM  80
#define QKV_N (3 * HID)   // 3840
#define SEG   256
#define NSEG  8

// ---------------- device scratch ----------------
__device__ __align__(256) float g_qkv[S_LEN * QKV_N];
__device__ __align__(256) __half g_xh[S_LEN * HID];
__device__ __align__(256) __half g_xl[S_LEN * HID];
__device__ __align__(256) __half g_ah[S_LEN * HID];
__device__ __align__(256) __half g_al[S_LEN * HID];
__device__ __align__(256) __half g_wq[QKV_N * HID];   // [N][K] fp16
__device__ __align__(256) __half g_wo[HID * HID];
__device__ __align__(256) __half g_qh[S_LEN * HID];
__device__ __align__(256) __half g_ql[S_LEN * HID];
__device__ __align__(256) __half g_kh[S_LEN * HID];
__device__ __align__(256) __half g_vh[S_LEN * HID];

__device__ __forceinline__ uint32_t smem_to_u32(const void* p) {
    uint32_t a;
    asm("{ .reg .u64 t; cvta.to.shared.u64 t, %1; cvt.u32.u64 %0, t; }"
        : "=r"(a) : "l"(p));
    return a;
}

#define CP_ASYNC16(sa, gp) \
    asm volatile("cp.async.cg.shared.global [%0], [%1], 16;" \
        :: "r"(sa), "l"(gp) : "memory")
#define CP_COMMIT() asm volatile("cp.async.commit_group;" ::: "memory")

#define MMA_F16(ac, a, b) \
    asm volatile("mma.sync.aligned.m16n8k16.row.col.f32.f16.f16.f32 " \
        "{%0,%1,%2,%3},{%4,%5,%6,%7},{%8,%9},{%0,%1,%2,%3};" \
        : "+f"((ac)[0]), "+f"((ac)[1]), "+f"((ac)[2]), "+f"((ac)[3]) \
        : "r"((a)[0]), "r"((a)[1]), "r"((a)[2]), "r"((a)[3]), \
          "r"((b)[0]), "r"((b)[1]))

#define LDSM_X4(r0, r1, r2, r3, addr) \
    asm volatile("ldmatrix.sync.aligned.m8n8.x4.shared.b16 {%0,%1,%2,%3}, [%4];" \
        : "=r"(r0), "=r"(r1), "=r"(r2), "=r"(r3) : "r"(addr))
#define LDSM_X4T(r0, r1, r2, r3, addr) \
    asm volatile("ldmatrix.sync.aligned.m8n8.x4.trans.shared.b16 {%0,%1,%2,%3}, [%4];" \
        : "=r"(r0), "=r"(r1), "=r"(r2), "=r"(r3) : "r"(addr))
#define LDSM_X2T(r0, r1, addr) \
    asm volatile("ldmatrix.sync.aligned.m8n8.x2.trans.shared.b16 {%0,%1}, [%2];" \
        : "=r"(r0), "=r"(r1) : "r"(addr))

// split float2 -> packed fp16 hi and lo (low half = .x)
__device__ __forceinline__ void split2h(float2 p, uint32_t& hi, uint32_t& lo) {
    __half hx = __float2half_rn(p.x);
    __half hy = __float2half_rn(p.y);
    __half lx = __float2half_rn(p.x - __half2float(hx));
    __half ly = __float2half_rn(p.y - __half2float(hy));
    hi = (uint32_t)__half_as_ushort(hx) | ((uint32_t)__half_as_ushort(hy) << 16);
    lo = (uint32_t)__half_as_ushort(lx) | ((uint32_t)__half_as_ushort(ly) << 16);
}

// ---------------------------------------------------------------------------
// Prep kernels
// ---------------------------------------------------------------------------
__global__ void split_h_kernel(const float* __restrict__ src,
                               __half* __restrict__ hi,
                               __half* __restrict__ lo, int n) {
    int i = blockIdx.x * blockDim.x + threadIdx.x;
    if (i >= n) return;
    float a = src[i];
    __half h = __float2half_rn(a);
    hi[i] = h;
    lo[i] = __float2half_rn(a - __half2float(h));
}

// W [K][N] fp32 -> Wt [N][K] fp16 (rounded)
__global__ void transpose_h_kernel(const float* __restrict__ W,
                                   __half* __restrict__ Wt,
                                   int K, int N) {
    __shared__ float t[32][33];
    int bn = blockIdx.x, bk = blockIdx.y;
    int tx = threadIdx.x, ty = threadIdx.y;   // 32 x 8
#pragma unroll
    for (int i = 0; i < 4; i++)
        t[ty + i * 8][tx] = W[(size_t)(bk * 32 + ty + i * 8) * N + bn * 32 + tx];
    __syncthreads();
#pragma unroll
    for (int i = 0; i < 4; i++)
        Wt[(size_t)(bn * 32 + ty + i * 8) * K + bk * 32 + tx] =
            __float2half_rn(t[tx][ty + i * 8]);
}

// rope on q,k: q -> qh/ql (split, scale folded), k -> kh (single fp16)
__global__ void rope_split_kernel(const float* __restrict__ qkv,
                                  const float* __restrict__ cosb,
                                  const float* __restrict__ sinb,
                                  __half* __restrict__ qh,
                                  __half* __restrict__ ql,
                                  __half* __restrict__ kh) {
    int idx = blockIdx.x * blockDim.x + threadIdx.x;
    const int total = S_LEN * NHEAD * 40;
    if (idx >= total) return;
    int s   = idx / (NHEAD * 40);
    int rem = idx % (NHEAD * 40);
    int h   = rem / 40;
    int d   = rem % 40;
    const float scale = rsqrtf((float)HDIM);

    float c1 = cosb[s * HDIM + d],      s1 = sinb[s * HDIM + d];
    float c2 = cosb[s * HDIM + d + 40], s2 = sinb[s * HDIM + d + 40];

    size_t gb = (size_t)s * QKV_N + h * HDIM + d;
    size_t ob = (size_t)s * HID + h * HDIM + d;

    float q1 = qkv[gb], q2 = qkv[gb + 40];
    float qa = (q1 * c1 - q2 * s1) * scale;
    float qb = (q2 * c2 + q1 * s2) * scale;
    float k1 = qkv[gb + HID], k2 = qkv[gb + HID + 40];

    __half t;
    t = __float2half_rn(qa); qh[ob] = t;      ql[ob]      = __float2half_rn(qa - __half2float(t));
    t = __float2half_rn(qb); qh[ob + 40] = t; ql[ob + 40] = __float2half_rn(qb - __half2float(t));
    kh[ob]      = __float2half_rn(k1 * c1 - k2 * s1);
    kh[ob + 40] = __float2half_rn(k2 * c2 + k1 * s2);
}

__global__ void vsplit_kernel(const float* __restrict__ qkv,
                              __half* __restrict__ vh) {
    int idx = blockIdx.x * blockDim.x + threadIdx.x;
    if (idx >= S_LEN * HID) return;
    int s = idx / HID, j = idx % HID;
    vh[idx] = __float2half_rn(qkv[(size_t)s * QKV_N + 2 * HID + j]);
}

// ---------------------------------------------------------------------------
// fp16 2-product GEMM: C[M,N] = (Ah+Al)[M,K] @ B[N,K]^T + bias
// 128x128 tile, BK=32, 2-stage cp.async, 2 CTA/SM.
// ---------------------------------------------------------------------------
#define GBK        32
#define ROW_B      80
#define TILE_B     (128 * ROW_B)            // 10240
#define STAGE_B    (3 * TILE_B)             // 30720
#define G_SMEM     (2 * STAGE_B)            // 61440

__global__ __launch_bounds__(256, 2)
void gemm_f16x2_kernel(int M, int N, int K,
                       const __half* __restrict__ Ah,
                       const __half* __restrict__ Al,
                       const __half* __restrict__ B,
                       const float* __restrict__ bias,
                       float* __restrict__ C) {
    extern __shared__ __align__(16) char smem[];
    const uint32_t sbase = smem_to_u32(smem);

    const int tid  = threadIdx.x;
    const int wid  = tid >> 5;
    const int lane = tid & 31;
    const int g    = lane >> 2;
    const int tig  = lane & 3;
    const int wm   = wid & 1;
    const int wn   = wid >> 1;
    const int n0   = blockIdx.x * 128;
    const int m0   = blockIdx.y * 128;

    const __half* srcs[3] = {
        Ah + (size_t)m0 * K, Al + (size_t)m0 * K, B + (size_t)n0 * K };

    float acc[4][4][4];
#pragma unroll
    for (int i = 0; i < 4; i++)
#pragma unroll
        for (int j = 0; j < 4; j++)
#pragma unroll
            for (int r = 0; r < 4; r++) acc[i][j][r] = 0.f;

    const int KT = K / GBK;

    auto issue_stage = [&](int buf, int kt) {
#pragma unroll
        for (int i = 0; i < 6; i++) {
            int c    = tid + i * 256;
            int tile = c >> 9;
            int rem  = c & 511;
            int row  = rem >> 2;
            int c16  = rem & 3;
            const __half* gp = srcs[tile] + (size_t)row * K + kt * GBK + c16 * 8;
            uint32_t sa = sbase + buf * STAGE_B + tile * TILE_B + row * ROW_B + c16 * 16;
            CP_ASYNC16(sa, gp);
        }
        CP_COMMIT();
    };

    const uint32_t aOff = (uint32_t)(wm * 64 + (lane & 15)) * ROW_B + ((lane >> 4) & 1) * 16;
    const uint32_t bOff = (uint32_t)(wn * 32 + (lane & 15)) * ROW_B + ((lane >> 4) & 1) * 16;

    issue_stage(0, 0);

    for (int kt = 0; kt < KT; kt++) {
        const int buf = kt & 1;
        if (kt + 1 < KT) {
            issue_stage(buf ^ 1, kt + 1);
            asm volatile("cp.async.wait_group 1;" ::: "memory");
        } else {
            asm volatile("cp.async.wait_group 0;" ::: "memory");
        }
        __syncthreads();

        const uint32_t stage = sbase + buf * STAGE_B;
        const uint32_t aAh = stage + aOff;
        const uint32_t aAl = aAh + TILE_B;
        const uint32_t aB  = stage + 2 * TILE_B + bOff;

#pragma unroll
        for (int ks = 0; ks < 2; ks++) {
            const uint32_t ko = ks * 32;
            uint32_t bq[4][2];
#pragma unroll
            for (int np = 0; np < 2; np++)
                LDSM_X4(bq[np*2][0], bq[np*2+1][0], bq[np*2][1], bq[np*2+1][1],
                        aB + np * (16 * ROW_B) + ko);
            uint32_t ah[4][4], al[4][4];
#pragma unroll
            for (int mt = 0; mt < 4; mt++) {
                LDSM_X4(ah[mt][0], ah[mt][1], ah[mt][2], ah[mt][3],
                        aAh + mt * (16 * ROW_B) + ko);
                LDSM_X4(al[mt][0], al[mt][1], al[mt][2], al[mt][3],
                        aAl + mt * (16 * ROW_B) + ko);
            }
#pragma unroll
            for (int mt = 0; mt < 4; mt++)
#pragma unroll
                for (int nt = 0; nt < 4; nt++) {
                    MMA_F16(acc[mt][nt], ah[mt], bq[nt]);
                    MMA_F16(acc[mt][nt], al[mt], bq[nt]);
                }
        }
        __syncthreads();
    }

#pragma unroll
    for (int mt = 0; mt < 4; mt++) {
        const int row0 = m0 + wm * 64 + mt * 16 + g;
#pragma unroll
        for (int nt = 0; nt < 4; nt++) {
            const int col = n0 + wn * 32 + nt * 8 + tig * 2;
            const float b0 = bias[col], b1 = bias[col + 1];
            float2 v0 = make_float2(acc[mt][nt][0] + b0, acc[mt][nt][1] + b1);
            float2 v1 = make_float2(acc[mt][nt][2] + b0, acc[mt][nt][3] + b1);
            *(float2*)&C[(size_t)row0 * N + col]       = v0;
            *(float2*)&C[(size_t)(row0 + 8) * N + col] = v1;
        }
    }
}

// ---------------------------------------------------------------------------
// HMMA attention, fp16 2-product. grid = (4 qtiles, 8 segs, 16 heads).
// q split (qh+ql), k/v single fp16; P split in regs.
// ---------------------------------------------------------------------------
#define AQROW   176
#define ASS_LD  268
#define SM_QH   0
#define SM_QL   11264
#define SM_K    22528                     // 256*176 = 45056; reused for V
#define SM_SS   67584
#define ATTN_SMEM (67584 + 64 * ASS_LD * 4)   // 136192

__global__ __launch_bounds__(256, 1)
void attn_mma_kernel(const __half* __restrict__ qh_g,
                     const __half* __restrict__ ql_g,
                     const __half* __restrict__ kh_g,
                     const __half* __restrict__ vh_g,
                     const int* __restrict__ cu,
                     __half* __restrict__ oh,
                     __half* __restrict__ ol) {
    extern __shared__ __align__(16) char sm[];
    const uint32_t sb = smem_to_u32(sm);
    float* sS = (float*)(sm + SM_SS);

    const int tid  = threadIdx.x;
    const int wid  = tid >> 5;
    const int lane = tid & 31;
    const int qt   = blockIdx.x;
    const int seg  = blockIdx.y;
    const int head = blockIdx.z;

    const int segStart = cu[seg];
    const int q0 = segStart + qt * 64;
    const int hb = head * HDIM;

    // ---- load q hi/lo (64x80) and k (256x80)
    for (int i = tid; i < 640; i += 256) {
        int r = i / 10, c = i % 10;
        const size_t go = (size_t)(q0 + r) * HID + hb + c * 8;
        *(uint4*)(sm + SM_QH + r * AQROW + c * 16) = *(const uint4*)(qh_g + go);
        *(uint4*)(sm + SM_QL + r * AQROW + c * 16) = *(const uint4*)(ql_g + go);
    }
    for (int i = tid; i < 2560; i += 256) {
        int r = i / 10, c = i % 10;
        const size_t go = (size_t)(segStart + r) * HID + hb + c * 8;
        *(uint4*)(sm + SM_K + r * AQROW + c * 16) = *(const uint4*)(kh_g + go);
    }
    __syncthreads();

    // ---- QK^T: warp grid 2(m) x 4(n); warp tile 32 x 64
    {
        const int wm = wid & 1, wn = wid >> 1;
        float acc[2][8][4];
#pragma unroll
        for (int i = 0; i < 2; i++)
#pragma unroll
            for (int j = 0; j < 8; j++)
#pragma unroll
                for (int r = 0; r < 4; r++) acc[i][j][r] = 0.f;

        const uint32_t aBase = sb + SM_QH + (uint32_t)(wm * 32 + (lane & 15)) * AQROW
                               + ((lane >> 4) & 1) * 16;
        const uint32_t bBase = sb + SM_K + (uint32_t)(wn * 64 + (lane & 15)) * AQROW
                               + ((lane >> 4) & 1) * 16;

#pragma unroll
        for (int ks = 0; ks < 5; ks++) {
            const uint32_t ko = ks * 32;
            uint32_t ah[2][4], al[2][4];
#pragma unroll
            for (int mt = 0; mt < 2; mt++) {
                LDSM_X4(ah[mt][0], ah[mt][1], ah[mt][2], ah[mt][3],
                        aBase + mt * (16 * AQROW) + ko);
                LDSM_X4(al[mt][0], al[mt][1], al[mt][2], al[mt][3],
                        aBase + (SM_QL - SM_QH) + mt * (16 * AQROW) + ko);
            }
#pragma unroll
            for (int np = 0; np < 4; np++) {
                uint32_t bk[2][2];
                LDSM_X4(bk[0][0], bk[1][0], bk[0][1], bk[1][1],
                        bBase + np * (16 * AQROW) + ko);
#pragma unroll
                for (int mt = 0; mt < 2; mt++)
#pragma unroll
                    for (int j = 0; j < 2; j++) {
                        MMA_F16(acc[mt][np*2+j], ah[mt], bk[j]);
                        MMA_F16(acc[mt][np*2+j], al[mt], bk[j]);
                    }
            }
        }
#pragma unroll
        for (int mt = 0; mt < 2; mt++) {
            const int r = wm * 32 + mt * 16 + (lane >> 2);
#pragma unroll
            for (int nt = 0; nt < 8; nt++) {
                const int c = wn * 64 + nt * 8 + 2 * (lane & 3);
                *(float2*)&sS[r * ASS_LD + c] =
                    make_float2(acc[mt][nt][0], acc[mt][nt][1]);
                *(float2*)&sS[(r + 8) * ASS_LD + c] =
                    make_float2(acc[mt][nt][2], acc[mt][nt][3]);
            }
        }
    }
    __syncthreads();

    // ---- load V (overlay K) + softmax
    for (int i = tid; i < 2560; i += 256) {
        int r = i / 10, c = i % 10;
        const size_t go = (size_t)(segStart + r) * HID + hb + c * 8;
        *(uint4*)(sm + SM_K + r * AQROW + c * 16) = *(const uint4*)(vh_g + go);
    }
    {
        const int r  = tid >> 2;
        const int cl = tid & 3;
        float mx = -1e30f;
#pragma unroll
        for (int j = 0; j < 64; j++)
            mx = fmaxf(mx, sS[r * ASS_LD + cl + 4 * j]);
        mx = fmaxf(mx, __shfl_xor_sync(0xFFFFFFFFu, mx, 1));
        mx = fmaxf(mx, __shfl_xor_sync(0xFFFFFFFFu, mx, 2));
        float sum = 0.f;
#pragma unroll
        for (int j = 0; j < 64; j++) {
            int c = cl + 4 * j;
            float e = __expf(sS[r * ASS_LD + c] - mx);
            sS[r * ASS_LD + c] = e;
            sum += e;
        }
        sum += __shfl_xor_sync(0xFFFFFFFFu, sum, 1);
        sum += __shfl_xor_sync(0xFFFFFFFFu, sum, 2);
        float inv = 1.f / sum;
#pragma unroll
        for (int j = 0; j < 64; j++) sS[r * ASS_LD + cl + 4 * j] *= inv;
    }
    __syncthreads();

    // ---- PV: warp grid 4(m) x 2(n); warp tile 16 rows x 40 d-cols
    {
        const int wr = wid >> 1, wc = wid & 1;
        float facc[5][4];
#pragma unroll
        for (int i = 0; i < 5; i++)
#pragma unroll
            for (int r = 0; r < 4; r++) facc[i][r] = 0.f;

        const int pr = wr * 16 + (lane >> 2);
        const uint32_t vRowOff = (uint32_t)((lane & 7) + ((lane >> 3) & 1) * 8) * AQROW;
        const uint32_t vColHi  = ((lane >> 4) & 1) * 16;

#pragma unroll
        for (int ks = 0; ks < 16; ks++) {
            const int c = ks * 16 + 2 * (lane & 3);
            float2 p00 = *(float2*)&sS[pr * ASS_LD + c];
            float2 p01 = *(float2*)&sS[pr * ASS_LD + c + 8];
            float2 p10 = *(float2*)&sS[(pr + 8) * ASS_LD + c];
            float2 p11 = *(float2*)&sS[(pr + 8) * ASS_LD + c + 8];
            uint32_t pha[4], pla[4];
            split2h(p00, pha[0], pla[0]);
            split2h(p10, pha[1], pla[1]);
            split2h(p01, pha[2], pla[2]);
            split2h(p11, pha[3], pla[3]);

            const uint32_t vk = sb + SM_K + (uint32_t)(ks * 16) * AQROW + vRowOff;

#pragma unroll
            for (int np = 0; np < 2; np++) {
                const uint32_t co = (uint32_t)(wc * 40 + np * 16) * 2 + vColHi;
                uint32_t bv[2][2];
                LDSM_X4T(bv[0][0], bv[0][1], bv[1][0], bv[1][1], vk + co);
#pragma unroll
                for (int j = 0; j < 2; j++) {
                    MMA_F16(facc[np*2+j], pha, bv[j]);
                    MMA_F16(facc[np*2+j], pla, bv[j]);
                }
            }
            {   // nt = 4 via x2.trans
                const uint32_t co = (uint32_t)(wc * 40 + 32) * 2;
                uint32_t b4[2];
                LDSM_X2T(b4[0], b4[1], vk + co);
                MMA_F16(facc[4], pha, b4);
                MMA_F16(facc[4], pla, b4);
            }
        }

        // epilogue: fp16 hi/lo split
        const int row0 = q0 + wr * 16 + (lane >> 2);
#pragma unroll
        for (int nt = 0; nt < 5; nt++) {
            const int col = hb + wc * 40 + nt * 8 + 2 * (lane & 3);
            uint32_t h0, l0, h1, l1;
            split2h(make_float2(facc[nt][0], facc[nt][1]), h0, l0);
            split2h(make_float2(facc[nt][2], facc[nt][3]), h1, l1);
            *(uint32_t*)(oh + (size_t)row0 * HID + col)       = h0;
            *(uint32_t*)(ol + (size_t)row0 * HID + col)       = l0;
            *(uint32_t*)(oh + (size_t)(row0 + 8) * HID + col) = h1;
            *(uint32_t*)(ol + (size_t)(row0 + 8) * HID + col) = l1;
        }
    }
}

// ---------------------------------------------------------------------------
extern "C" void kernel_launch(void* const* d_in, const int* in_sizes, int n_in,
                              void* d_out, int out_size) {
    const float* x      = (const float*)d_in[0];
    const float* cosb   = (const float*)d_in[1];
    const float* sinb   = (const float*)d_in[2];
    const float* W_qkv  = (const float*)d_in[3];
    const float* b_qkv  = (const float*)d_in[4];
    const float* W_out  = (const float*)d_in[5];
    const float* b_out  = (const float*)d_in[6];
    const int*   cu     = (const int*)d_in[7];
    float*       outp   = (float*)d_out;

    float* qkv;
    __half *xh, *xl, *ah, *al, *wq, *wo, *qh, *ql, *kh, *vh;
    cudaGetSymbolAddress((void**)&qkv, g_qkv);
    cudaGetSymbolAddress((void**)&xh,  g_xh);
    cudaGetSymbolAddress((void**)&xl,  g_xl);
    cudaGetSymbolAddress((void**)&ah,  g_ah);
    cudaGetSymbolAddress((void**)&al,  g_al);
    cudaGetSymbolAddress((void**)&wq,  g_wq);
    cudaGetSymbolAddress((void**)&wo,  g_wo);
    cudaGetSymbolAddress((void**)&qh,  g_qh);
    cudaGetSymbolAddress((void**)&ql,  g_ql);
    cudaGetSymbolAddress((void**)&kh,  g_kh);
    cudaGetSymbolAddress((void**)&vh,  g_vh);

    static bool attr_set = false;
    if (!attr_set) {
        cudaFuncSetAttribute(attn_mma_kernel,
                             cudaFuncAttributeMaxDynamicSharedMemorySize, ATTN_SMEM);
        cudaFuncSetAttribute(gemm_f16x2_kernel,
                             cudaFuncAttributeMaxDynamicSharedMemorySize, G_SMEM);
        attr_set = true;
    }

    // 0. prep
    {
        int n = S_LEN * HID;
        split_h_kernel<<<(n + 255) / 256, 256>>>(x, xh, xl, n);
        dim3 tb(32, 8);
        transpose_h_kernel<<<dim3(QKV_N / 32, HID / 32), tb>>>(W_qkv, wq, HID, QKV_N);
        transpose_h_kernel<<<dim3(HID / 32, HID / 32), tb>>>(W_out, wo, HID, HID);
    }
    // 1. QKV projection
    gemm_f16x2_kernel<<<dim3(QKV_N / 128, S_LEN / 128), 256, G_SMEM>>>(
        S_LEN, QKV_N, HID, xh, xl, wq, b_qkv, qkv);
    // 2. rope + splits
    {
        int t1 = S_LEN * NHEAD * 40;
        rope_split_kernel<<<(t1 + 255) / 256, 256>>>(qkv, cosb, sinb, qh, ql, kh);
        int t2 = S_LEN * HID;
        vsplit_kernel<<<(t2 + 255) / 256, 256>>>(qkv, vh);
    }
    // 3. HMMA attention -> ah/al
    attn_mma_kernel<<<dim3(4, NSEG, NHEAD), 256, ATTN_SMEM>>>(
        qh, ql, kh, vh, cu, ah, al);
    // 4. out projection
    gemm_f16x2_kernel<<<dim3(HID / 128, S_LEN / 128), 256, G_SMEM>>>(
        S_LEN, HID, HID, ah, al, wo, b_out, outp);
}

// round 8
// speedup vs baseline: 1.6873x; 1.0598x over previous
#include <cuda_runtime.h>
#include <cuda_fp16.h>
#include <cstdint>
#include <math.h>

// ===========================================================================
// VisionAttention (sm_103): fp16 2-product HMMA GEMMs + persistent-segment
// HMMA attention with fused rope/splits. 6 launches total.
// ===========================================================================

#define S_LEN 2048
#define HID   1280
#define NHEAD 16
#define HDIM  80
#define QKV_N (3 * HID)   // 3840
#define SEG   256
#define NSEG  8

// ---------------- device scratch ----------------
__device__ __align__(256) float g_qkv[S_LEN * QKV_N];
__device__ __align__(256) __half g_xh[S_LEN * HID];
__device__ __align__(256) __half g_xl[S_LEN * HID];
__device__ __align__(256) __half g_ah[S_LEN * HID];
__device__ __align__(256) __half g_al[S_LEN * HID];
__device__ __align__(256) __half g_wq[QKV_N * HID];   // [N][K] fp16
__device__ __align__(256) __half g_wo[HID * HID];

__device__ __forceinline__ uint32_t smem_to_u32(const void* p) {
    uint32_t a;
    asm("{ .reg .u64 t; cvta.to.shared.u64 t, %1; cvt.u32.u64 %0, t; }"
        : "=r"(a) : "l"(p));
    return a;
}

#define CP_ASYNC16(sa, gp) \
    asm volatile("cp.async.cg.shared.global [%0], [%1], 16;" \
        :: "r"(sa), "l"(gp) : "memory")
#define CP_COMMIT() asm volatile("cp.async.commit_group;" ::: "memory")

#define MMA_F16(ac, a, b) \
    asm volatile("mma.sync.aligned.m16n8k16.row.col.f32.f16.f16.f32 " \
        "{%0,%1,%2,%3},{%4,%5,%6,%7},{%8,%9},{%0,%1,%2,%3};" \
        : "+f"((ac)[0]), "+f"((ac)[1]), "+f"((ac)[2]), "+f"((ac)[3]) \
        : "r"((a)[0]), "r"((a)[1]), "r"((a)[2]), "r"((a)[3]), \
          "r"((b)[0]), "r"((b)[1]))

#define LDSM_X4(r0, r1, r2, r3, addr) \
    asm volatile("ldmatrix.sync.aligned.m8n8.x4.shared.b16 {%0,%1,%2,%3}, [%4];" \
        : "=r"(r0), "=r"(r1), "=r"(r2), "=r"(r3) : "r"(addr))
#define LDSM_X4T(r0, r1, r2, r3, addr) \
    asm volatile("ldmatrix.sync.aligned.m8n8.x4.trans.shared.b16 {%0,%1,%2,%3}, [%4];" \
        : "=r"(r0), "=r"(r1), "=r"(r2), "=r"(r3) : "r"(addr))
#define LDSM_X2T(r0, r1, addr) \
    asm volatile("ldmatrix.sync.aligned.m8n8.x2.trans.shared.b16 {%0,%1}, [%2];" \
        : "=r"(r0), "=r"(r1) : "r"(addr))

__device__ __forceinline__ void split2h(float2 p, uint32_t& hi, uint32_t& lo) {
    __half hx = __float2half_rn(p.x);
    __half hy = __float2half_rn(p.y);
    __half lx = __float2half_rn(p.x - __half2float(hx));
    __half ly = __float2half_rn(p.y - __half2float(hy));
    hi = (uint32_t)__half_as_ushort(hx) | ((uint32_t)__half_as_ushort(hy) << 16);
    lo = (uint32_t)__half_as_ushort(lx) | ((uint32_t)__half_as_ushort(ly) << 16);
}

// ---------------------------------------------------------------------------
// Prep kernels
// ---------------------------------------------------------------------------
__global__ void split_h_kernel(const float* __restrict__ src,
                               __half* __restrict__ hi,
                               __half* __restrict__ lo, int n) {
    int i = blockIdx.x * blockDim.x + threadIdx.x;
    if (i >= n) return;
    float a = src[i];
    __half h = __float2half_rn(a);
    hi[i] = h;
    lo[i] = __float2half_rn(a - __half2float(h));
}

// W [K][N] fp32 -> Wt [N][K] fp16
__global__ void transpose_h_kernel(const float* __restrict__ W,
                                   __half* __restrict__ Wt,
                                   int K, int N) {
    __shared__ float t[32][33];
    int bn = blockIdx.x, bk = blockIdx.y;
    int tx = threadIdx.x, ty = threadIdx.y;
#pragma unroll
    for (int i = 0; i < 4; i++)
        t[ty + i * 8][tx] = W[(size_t)(bk * 32 + ty + i * 8) * N + bn * 32 + tx];
    __syncthreads();
#pragma unroll
    for (int i = 0; i < 4; i++)
        Wt[(size_t)(bn * 32 + ty + i * 8) * K + bk * 32 + tx] =
            __float2half_rn(t[tx][ty + i * 8]);
}

// ---------------------------------------------------------------------------
// fp16 2-product GEMM: C[M,N] = (Ah+Al)[M,K] @ B[N,K]^T + bias
// 128x128 tile, BK=32, 2-stage cp.async, 2 CTA/SM.  (R7 config, unchanged)
// ---------------------------------------------------------------------------
#define GBK        32
#define ROW_B      80
#define TILE_B     (128 * ROW_B)
#define STAGE_B    (3 * TILE_B)
#define G_SMEM     (2 * STAGE_B)

__global__ __launch_bounds__(256, 2)
void gemm_f16x2_kernel(int M, int N, int K,
                       const __half* __restrict__ Ah,
                       const __half* __restrict__ Al,
                       const __half* __restrict__ B,
                       const float* __restrict__ bias,
                       float* __restrict__ C) {
    extern __shared__ __align__(16) char smem[];
    const uint32_t sbase = smem_to_u32(smem);

    const int tid  = threadIdx.x;
    const int wid  = tid >> 5;
    const int lane = tid & 31;
    const int g    = lane >> 2;
    const int tig  = lane & 3;
    const int wm   = wid & 1;
    const int wn   = wid >> 1;
    const int n0   = blockIdx.x * 128;
    const int m0   = blockIdx.y * 128;

    const __half* srcs[3] = {
        Ah + (size_t)m0 * K, Al + (size_t)m0 * K, B + (size_t)n0 * K };

    float acc[4][4][4];
#pragma unroll
    for (int i = 0; i < 4; i++)
#pragma unroll
        for (int j = 0; j < 4; j++)
#pragma unroll
            for (int r = 0; r < 4; r++) acc[i][j][r] = 0.f;

    const int KT = K / GBK;

    auto issue_stage = [&](int buf, int kt) {
#pragma unroll
        for (int i = 0; i < 6; i++) {
            int c    = tid + i * 256;
            int tile = c >> 9;
            int rem  = c & 511;
            int row  = rem >> 2;
            int c16  = rem & 3;
            const __half* gp = srcs[tile] + (size_t)row * K + kt * GBK + c16 * 8;
            uint32_t sa = sbase + buf * STAGE_B + tile * TILE_B + row * ROW_B + c16 * 16;
            CP_ASYNC16(sa, gp);
        }
        CP_COMMIT();
    };

    const uint32_t aOff = (uint32_t)(wm * 64 + (lane & 15)) * ROW_B + ((lane >> 4) & 1) * 16;
    const uint32_t bOff = (uint32_t)(wn * 32 + (lane & 15)) * ROW_B + ((lane >> 4) & 1) * 16;

    issue_stage(0, 0);

    for (int kt = 0; kt < KT; kt++) {
        const int buf = kt & 1;
        if (kt + 1 < KT) {
            issue_stage(buf ^ 1, kt + 1);
            asm volatile("cp.async.wait_group 1;" ::: "memory");
        } else {
            asm volatile("cp.async.wait_group 0;" ::: "memory");
        }
        __syncthreads();

        const uint32_t stage = sbase + buf * STAGE_B;
        const uint32_t aAh = stage + aOff;
        const uint32_t aAl = aAh + TILE_B;
        const uint32_t aB  = stage + 2 * TILE_B + bOff;

#pragma unroll
        for (int ks = 0; ks < 2; ks++) {
            const uint32_t ko = ks * 32;
            uint32_t bq[4][2];
#pragma unroll
            for (int np = 0; np < 2; np++)
                LDSM_X4(bq[np*2][0], bq[np*2+1][0], bq[np*2][1], bq[np*2+1][1],
                        aB + np * (16 * ROW_B) + ko);
            uint32_t ah[4][4], al[4][4];
#pragma unroll
            for (int mt = 0; mt < 4; mt++) {
                LDSM_X4(ah[mt][0], ah[mt][1], ah[mt][2], ah[mt][3],
                        aAh + mt * (16 * ROW_B) + ko);
                LDSM_X4(al[mt][0], al[mt][1], al[mt][2], al[mt][3],
                        aAl + mt * (16 * ROW_B) + ko);
            }
#pragma unroll
            for (int mt = 0; mt < 4; mt++)
#pragma unroll
                for (int nt = 0; nt < 4; nt++) {
                    MMA_F16(acc[mt][nt], ah[mt], bq[nt]);
                    MMA_F16(acc[mt][nt], al[mt], bq[nt]);
                }
        }
        __syncthreads();
    }

#pragma unroll
    for (int mt = 0; mt < 4; mt++) {
        const int row0 = m0 + wm * 64 + mt * 16 + g;
#pragma unroll
        for (int nt = 0; nt < 4; nt++) {
            const int col = n0 + wn * 32 + nt * 8 + tig * 2;
            const float b0 = bias[col], b1 = bias[col + 1];
            float2 v0 = make_float2(acc[mt][nt][0] + b0, acc[mt][nt][1] + b1);
            float2 v1 = make_float2(acc[mt][nt][2] + b0, acc[mt][nt][3] + b1);
            *(float2*)&C[(size_t)row0 * N + col]       = v0;
            *(float2*)&C[(size_t)(row0 + 8) * N + col] = v1;
        }
    }
}

// ---------------------------------------------------------------------------
// Persistent-segment HMMA attention with fused rope + fp16 splits.
// grid = (8 segs, 16 heads) = 128 CTAs (single wave). 256 threads.
// K/V loaded once; loop over 4 q-chunks of 64 rows.
// ---------------------------------------------------------------------------
#define AQROW   176                        // bytes per 80-half row (88 halves)
#define AQH     88                         // halves per row
#define ASS_LD  268
#define SM_K    0                          // 256*176 = 45056
#define SM_V    45056                      // 45056
#define SM_QH   90112                      // 64*176 = 11264
#define SM_QL   101376                     // 11264
#define SM_SS   112640                     // 64*268*4 = 68608
#define ATTN_SMEM (112640 + 64 * ASS_LD * 4)   // 181248

__global__ __launch_bounds__(256, 1)
void attn_mma_kernel(const float* __restrict__ qkv,
                     const float* __restrict__ cosb,
                     const float* __restrict__ sinb,
                     const int* __restrict__ cu,
                     __half* __restrict__ oh,
                     __half* __restrict__ ol) {
    extern __shared__ __align__(16) char sm[];
    const uint32_t sb = smem_to_u32(sm);
    float* sS = (float*)(sm + SM_SS);

    const int tid  = threadIdx.x;
    const int wid  = tid >> 5;
    const int lane = tid & 31;
    const int seg  = blockIdx.x;
    const int head = blockIdx.y;

    const int segStart = cu[seg];
    const int hb = head * HDIM;
    const float scale = rsqrtf((float)HDIM);

    // ---- load K with fused rope (fp32 -> rotate -> fp16 smem)
    for (int i = tid; i < SEG * 40; i += 256) {
        int r = i / 40, d = i % 40;
        int s = segStart + r;
        float c1 = cosb[s * HDIM + d],      s1 = sinb[s * HDIM + d];
        float c2 = cosb[s * HDIM + d + 40], s2 = sinb[s * HDIM + d + 40];
        size_t gb = (size_t)s * QKV_N + HID + hb + d;
        float k1 = qkv[gb], k2 = qkv[gb + 40];
        __half* kp = (__half*)(sm + SM_K + r * AQROW);
        kp[d]      = __float2half_rn(k1 * c1 - k2 * s1);
        kp[d + 40] = __float2half_rn(k2 * c2 + k1 * s2);
    }
    // ---- load V (fp32 -> fp16)
    for (int i = tid; i < SEG * 20; i += 256) {
        int r = i / 20, c = i % 20;
        float4 v = *(const float4*)&qkv[(size_t)(segStart + r) * QKV_N + 2 * HID + hb + c * 4];
        __half2* vp = (__half2*)(sm + SM_V + r * AQROW + c * 8);
        vp[0] = __floats2half2_rn(v.x, v.y);
        vp[1] = __floats2half2_rn(v.z, v.w);
    }

    for (int chunk = 0; chunk < 4; chunk++) {
        const int q0 = segStart + chunk * 64;

        // ---- load q chunk: rope + scale + hi/lo split
        for (int i = tid; i < 64 * 40; i += 256) {
            int r = i / 40, d = i % 40;
            int s = q0 + r;
            float c1 = cosb[s * HDIM + d],      s1 = sinb[s * HDIM + d];
            float c2 = cosb[s * HDIM + d + 40], s2 = sinb[s * HDIM + d + 40];
            size_t gb = (size_t)s * QKV_N + hb + d;
            float q1 = qkv[gb], q2 = qkv[gb + 40];
            float qa = (q1 * c1 - q2 * s1) * scale;
            float qb = (q2 * c2 + q1 * s2) * scale;
            __half* qhp = (__half*)(sm + SM_QH + r * AQROW);
            __half* qlp = (__half*)(sm + SM_QL + r * AQROW);
            __half t;
            t = __float2half_rn(qa); qhp[d]      = t; qlp[d]      = __float2half_rn(qa - __half2float(t));
            t = __float2half_rn(qb); qhp[d + 40] = t; qlp[d + 40] = __float2half_rn(qb - __half2float(t));
        }
        __syncthreads();   // q (and, first iter, K/V) ready; prev PV done with sS

        // ---- QK^T: warp grid 2(m) x 4(n); warp tile 32 x 64
        {
            const int wm = wid & 1, wn = wid >> 1;
            float acc[2][8][4];
#pragma unroll
            for (int i = 0; i < 2; i++)
#pragma unroll
                for (int j = 0; j < 8; j++)
#pragma unroll
                    for (int r = 0; r < 4; r++) acc[i][j][r] = 0.f;

            const uint32_t aBase = sb + SM_QH + (uint32_t)(wm * 32 + (lane & 15)) * AQROW
                                   + ((lane >> 4) & 1) * 16;
            const uint32_t bBase = sb + SM_K + (uint32_t)(wn * 64 + (lane & 15)) * AQROW
                                   + ((lane >> 4) & 1) * 16;

#pragma unroll
            for (int ks = 0; ks < 5; ks++) {
                const uint32_t ko = ks * 32;
                uint32_t ah[2][4], al[2][4];
#pragma unroll
                for (int mt = 0; mt < 2; mt++) {
                    LDSM_X4(ah[mt][0], ah[mt][1], ah[mt][2], ah[mt][3],
                            aBase + mt * (16 * AQROW) + ko);
                    LDSM_X4(al[mt][0], al[mt][1], al[mt][2], al[mt][3],
                            aBase + (SM_QL - SM_QH) + mt * (16 * AQROW) + ko);
                }
#pragma unroll
                for (int np = 0; np < 4; np++) {
                    uint32_t bk[2][2];
                    LDSM_X4(bk[0][0], bk[1][0], bk[0][1], bk[1][1],
                            bBase + np * (16 * AQROW) + ko);
#pragma unroll
                    for (int mt = 0; mt < 2; mt++)
#pragma unroll
                        for (int j = 0; j < 2; j++) {
                            MMA_F16(acc[mt][np*2+j], ah[mt], bk[j]);
                            MMA_F16(acc[mt][np*2+j], al[mt], bk[j]);
                        }
                }
            }
#pragma unroll
            for (int mt = 0; mt < 2; mt++) {
                const int r = wm * 32 + mt * 16 + (lane >> 2);
#pragma unroll
                for (int nt = 0; nt < 8; nt++) {
                    const int c = wn * 64 + nt * 8 + 2 * (lane & 3);
                    *(float2*)&sS[r * ASS_LD + c] =
                        make_float2(acc[mt][nt][0], acc[mt][nt][1]);
                    *(float2*)&sS[(r + 8) * ASS_LD + c] =
                        make_float2(acc[mt][nt][2], acc[mt][nt][3]);
                }
            }
        }
        __syncthreads();

        // ---- softmax: 4 lanes per row
        {
            const int r  = tid >> 2;
            const int cl = tid & 3;
            float mx = -1e30f;
#pragma unroll
            for (int j = 0; j < 64; j++)
                mx = fmaxf(mx, sS[r * ASS_LD + cl + 4 * j]);
            mx = fmaxf(mx, __shfl_xor_sync(0xFFFFFFFFu, mx, 1));
            mx = fmaxf(mx, __shfl_xor_sync(0xFFFFFFFFu, mx, 2));
            float sum = 0.f;
#pragma unroll
            for (int j = 0; j < 64; j++) {
                int c = cl + 4 * j;
                float e = __expf(sS[r * ASS_LD + c] - mx);
                sS[r * ASS_LD + c] = e;
                sum += e;
            }
            sum += __shfl_xor_sync(0xFFFFFFFFu, sum, 1);
            sum += __shfl_xor_sync(0xFFFFFFFFu, sum, 2);
            float inv = 1.f / sum;
#pragma unroll
            for (int j = 0; j < 64; j++) sS[r * ASS_LD + cl + 4 * j] *= inv;
        }
        __syncthreads();

        // ---- PV: warp grid 4(m) x 2(n); warp tile 16 rows x 40 d-cols
        {
            const int wr = wid >> 1, wc = wid & 1;
            float facc[5][4];
#pragma unroll
            for (int i = 0; i < 5; i++)
#pragma unroll
                for (int r = 0; r < 4; r++) facc[i][r] = 0.f;

            const int pr = wr * 16 + (lane >> 2);
            const uint32_t vRowOff = (uint32_t)((lane & 7) + ((lane >> 3) & 1) * 8) * AQROW;
            const uint32_t vColHi  = ((lane >> 4) & 1) * 16;

#pragma unroll
            for (int ks = 0; ks < 16; ks++) {
                const int c = ks * 16 + 2 * (lane & 3);
                float2 p00 = *(float2*)&sS[pr * ASS_LD + c];
                float2 p01 = *(float2*)&sS[pr * ASS_LD + c + 8];
                float2 p10 = *(float2*)&sS[(pr + 8) * ASS_LD + c];
                float2 p11 = *(float2*)&sS[(pr + 8) * ASS_LD + c + 8];
                uint32_t pha[4], pla[4];
                split2h(p00, pha[0], pla[0]);
                split2h(p10, pha[1], pla[1]);
                split2h(p01, pha[2], pla[2]);
                split2h(p11, pha[3], pla[3]);

                const uint32_t vk = sb + SM_V + (uint32_t)(ks * 16) * AQROW + vRowOff;

#pragma unroll
                for (int np = 0; np < 2; np++) {
                    const uint32_t co = (uint32_t)(wc * 40 + np * 16) * 2 + vColHi;
                    uint32_t bv[2][2];
                    LDSM_X4T(bv[0][0], bv[0][1], bv[1][0], bv[1][1], vk + co);
#pragma unroll
                    for (int j = 0; j < 2; j++) {
                        MMA_F16(facc[np*2+j], pha, bv[j]);
                        MMA_F16(facc[np*2+j], pla, bv[j]);
                    }
                }
                {   // nt = 4 via x2.trans
                    const uint32_t co = (uint32_t)(wc * 40 + 32) * 2;
                    uint32_t b4[2];
                    LDSM_X2T(b4[0], b4[1], vk + co);
                    MMA_F16(facc[4], pha, b4);
                    MMA_F16(facc[4], pla, b4);
                }
            }

            const int row0 = q0 + wr * 16 + (lane >> 2);
#pragma unroll
            for (int nt = 0; nt < 5; nt++) {
                const int col = hb + wc * 40 + nt * 8 + 2 * (lane & 3);
                uint32_t h0, l0, h1, l1;
                split2h(make_float2(facc[nt][0], facc[nt][1]), h0, l0);
                split2h(make_float2(facc[nt][2], facc[nt][3]), h1, l1);
                *(uint32_t*)(oh + (size_t)row0 * HID + col)       = h0;
                *(uint32_t*)(ol + (size_t)row0 * HID + col)       = l0;
                *(uint32_t*)(oh + (size_t)(row0 + 8) * HID + col) = h1;
                *(uint32_t*)(ol + (size_t)(row0 + 8) * HID + col) = l1;
            }
        }
        __syncthreads();   // protect sS before next chunk's QK writes
    }
}

// ---------------------------------------------------------------------------
extern "C" void kernel_launch(void* const* d_in, const int* in_sizes, int n_in,
                              void* d_out, int out_size) {
    const float* x      = (const float*)d_in[0];
    const float* cosb   = (const float*)d_in[1];
    const float* sinb   = (const float*)d_in[2];
    const float* W_qkv  = (const float*)d_in[3];
    const float* b_qkv  = (const float*)d_in[4];
    const float* W_out  = (const float*)d_in[5];
    const float* b_out  = (const float*)d_in[6];
    const int*   cu     = (const int*)d_in[7];
    float*       outp   = (float*)d_out;

    float* qkv;
    __half *xh, *xl, *ah, *al, *wq, *wo;
    cudaGetSymbolAddress((void**)&qkv, g_qkv);
    cudaGetSymbolAddress((void**)&xh,  g_xh);
    cudaGetSymbolAddress((void**)&xl,  g_xl);
    cudaGetSymbolAddress((void**)&ah,  g_ah);
    cudaGetSymbolAddress((void**)&al,  g_al);
    cudaGetSymbolAddress((void**)&wq,  g_wq);
    cudaGetSymbolAddress((void**)&wo,  g_wo);

    static bool attr_set = false;
    if (!attr_set) {
        cudaFuncSetAttribute(attn_mma_kernel,
                             cudaFuncAttributeMaxDynamicSharedMemorySize, ATTN_SMEM);
        cudaFuncSetAttribute(gemm_f16x2_kernel,
                             cudaFuncAttributeMaxDynamicSharedMemorySize, G_SMEM);
        attr_set = true;
    }

    // 0. prep
    {
        int n = S_LEN * HID;
        split_h_kernel<<<(n + 255) / 256, 256>>>(x, xh, xl, n);
        dim3 tb(32, 8);
        transpose_h_kernel<<<dim3(QKV_N / 32, HID / 32), tb>>>(W_qkv, wq, HID, QKV_N);
        transpose_h_kernel<<<dim3(HID / 32, HID / 32), tb>>>(W_out, wo, HID, HID);
    }
    // 1. QKV projection
    gemm_f16x2_kernel<<<dim3(QKV_N / 128, S_LEN / 128), 256, G_SMEM>>>(
        S_LEN, QKV_N, HID, xh, xl, wq, b_qkv, qkv);
    // 2. attention (fused rope/splits) -> ah/al
    attn_mma_kernel<<<dim3(NSEG, NHEAD), 256, ATTN_SMEM>>>(
        qkv, cosb, sinb, cu, ah, al);
    // 3. out projection
    gemm_f16x2_kernel<<<dim3(HID / 128, S_LEN / 128), 256, G_SMEM>>>(
        S_LEN, HID, HID, ah, al, wo, b_out, outp);
}

// round 9
// speedup vs baseline: 1.8000x; 1.0668x over previous
#include <cuda_runtime.h>
#include <cuda_fp16.h>
#include <cstdint>
#include <math.h>

// ===========================================================================
// VisionAttention (sm_103): fp16 2-product HMMA GEMMs (BM templated;
// out-proj uses BM=64 for full-occupancy feeding) + persistent-segment
// HMMA attention with fused rope/splits. 4 launches total.
// ===========================================================================

#define S_LEN 2048
#define HID   1280
#define NHEAD 16
#define HDIM  80
#define QKV_N (3 * HID)   // 3840
#define SEG   256
#define NSEG  8

// ---------------- device scratch ----------------
__device__ __align__(256) float g_qkv[S_LEN * QKV_N];
__device__ __align__(256) __half g_xh[S_LEN * HID];
__device__ __align__(256) __half g_xl[S_LEN * HID];
__device__ __align__(256) __half g_ah[S_LEN * HID];
__device__ __align__(256) __half g_al[S_LEN * HID];
__device__ __align__(256) __half g_wq[QKV_N * HID];   // [N][K] fp16
__device__ __align__(256) __half g_wo[HID * HID];

__device__ __forceinline__ uint32_t smem_to_u32(const void* p) {
    uint32_t a;
    asm("{ .reg .u64 t; cvta.to.shared.u64 t, %1; cvt.u32.u64 %0, t; }"
        : "=r"(a) : "l"(p));
    return a;
}

#define CP_ASYNC16(sa, gp) \
    asm volatile("cp.async.cg.shared.global [%0], [%1], 16;" \
        :: "r"(sa), "l"(gp) : "memory")
#define CP_COMMIT() asm volatile("cp.async.commit_group;" ::: "memory")

#define MMA_F16(ac, a, b) \
    asm volatile("mma.sync.aligned.m16n8k16.row.col.f32.f16.f16.f32 " \
        "{%0,%1,%2,%3},{%4,%5,%6,%7},{%8,%9},{%0,%1,%2,%3};" \
        : "+f"((ac)[0]), "+f"((ac)[1]), "+f"((ac)[2]), "+f"((ac)[3]) \
        : "r"((a)[0]), "r"((a)[1]), "r"((a)[2]), "r"((a)[3]), \
          "r"((b)[0]), "r"((b)[1]))

#define LDSM_X4(r0, r1, r2, r3, addr) \
    asm volatile("ldmatrix.sync.aligned.m8n8.x4.shared.b16 {%0,%1,%2,%3}, [%4];" \
        : "=r"(r0), "=r"(r1), "=r"(r2), "=r"(r3) : "r"(addr))
#define LDSM_X4T(r0, r1, r2, r3, addr) \
    asm volatile("ldmatrix.sync.aligned.m8n8.x4.trans.shared.b16 {%0,%1,%2,%3}, [%4];" \
        : "=r"(r0), "=r"(r1), "=r"(r2), "=r"(r3) : "r"(addr))
#define LDSM_X2T(r0, r1, addr) \
    asm volatile("ldmatrix.sync.aligned.m8n8.x2.trans.shared.b16 {%0,%1}, [%2];" \
        : "=r"(r0), "=r"(r1) : "r"(addr))

__device__ __forceinline__ void split2h(float2 p, uint32_t& hi, uint32_t& lo) {
    __half hx = __float2half_rn(p.x);
    __half hy = __float2half_rn(p.y);
    __half lx = __float2half_rn(p.x - __half2float(hx));
    __half ly = __float2half_rn(p.y - __half2float(hy));
    hi = (uint32_t)__half_as_ushort(hx) | ((uint32_t)__half_as_ushort(hy) << 16);
    lo = (uint32_t)__half_as_ushort(lx) | ((uint32_t)__half_as_ushort(ly) << 16);
}

// ---------------------------------------------------------------------------
// Merged prep: 1 launch.
//   blocks [0, 2560)        : split x -> xh/xl (float4 vectorized)
//   blocks [2560, 7360)     : transpose W_qkv -> wq
//   blocks [7360, 8960)     : transpose W_out -> wo
// ---------------------------------------------------------------------------
__device__ __forceinline__ void transpose_tile(const float* __restrict__ W,
                                               __half* __restrict__ Wt,
                                               int K, int N, int bn, int bk,
                                               int tx, int ty, float* t /*[32*33]*/) {
#pragma unroll
    for (int i = 0; i < 4; i++)
        t[(ty + i * 8) * 33 + tx] = W[(size_t)(bk * 32 + ty + i * 8) * N + bn * 32 + tx];
    __syncthreads();
#pragma unroll
    for (int i = 0; i < 4; i++)
        Wt[(size_t)(bn * 32 + ty + i * 8) * K + bk * 32 + tx] =
            __float2half_rn(t[tx * 33 + ty + i * 8]);
}

__global__ void prep_kernel(const float* __restrict__ x,
                            const float* __restrict__ Wq,
                            const float* __restrict__ Wo,
                            __half* __restrict__ xh, __half* __restrict__ xl,
                            __half* __restrict__ wq, __half* __restrict__ wo) {
    __shared__ float t[32 * 33];
    const int b = blockIdx.x;
    const int tid = threadIdx.x;
    if (b < 2560) {
        int i = (b * 256 + tid) * 4;           // 2560*256*4 = 2,621,440 = S_LEN*HID
        float4 a = *(const float4*)&x[i];
        uint32_t h0, l0, h1, l1;
        split2h(make_float2(a.x, a.y), h0, l0);
        split2h(make_float2(a.z, a.w), h1, l1);
        ((uint32_t*)xh)[i >> 1]       = h0;
        ((uint32_t*)xh)[(i >> 1) + 1] = h1;
        ((uint32_t*)xl)[i >> 1]       = l0;
        ((uint32_t*)xl)[(i >> 1) + 1] = l1;
    } else if (b < 7360) {
        int j = b - 2560;                      // W_qkv: N=3840 -> 120 bn, K=1280 -> 40 bk
        transpose_tile(Wq, wq, HID, QKV_N, j % 120, j / 120, tid & 31, tid >> 5, t);
    } else {
        int j = b - 7360;                      // W_out: 40 x 40
        transpose_tile(Wo, wo, HID, HID, j % 40, j / 40, tid & 31, tid >> 5, t);
    }
}

// ---------------------------------------------------------------------------
// fp16 2-product GEMM, BM templated (128 or 64), BN=128, BK=32,
// 2-stage cp.async, 2 CTA/SM.
// ---------------------------------------------------------------------------
template <int BM>
__global__ __launch_bounds__(256, 2)
void gemm_f16x2_kernel(int M, int N, int K,
                       const __half* __restrict__ Ah,
                       const __half* __restrict__ Al,
                       const __half* __restrict__ B,
                       const float* __restrict__ bias,
                       float* __restrict__ C) {
    constexpr int MT      = BM / 32;           // m-tiles per warp
    constexpr int A_TILE  = BM * 80;
    constexpr int B_TILE  = 128 * 80;
    constexpr int STAGE   = 2 * A_TILE + B_TILE;
    constexpr int A_CHUNK = BM * 8;            // 16B chunks across both A tiles
    constexpr int CP_IT   = (A_CHUNK + 512) / 256;

    extern __shared__ __align__(16) char smem[];
    const uint32_t sbase = smem_to_u32(smem);

    const int tid  = threadIdx.x;
    const int wid  = tid >> 5;
    const int lane = tid & 31;
    const int g    = lane >> 2;
    const int tig  = lane & 3;
    const int wm   = wid & 1;
    const int wn   = wid >> 1;
    const int n0   = blockIdx.x * 128;
    const int m0   = blockIdx.y * BM;

    const __half* srcs[3] = {
        Ah + (size_t)m0 * K, Al + (size_t)m0 * K, B + (size_t)n0 * K };

    float acc[MT][4][4];
#pragma unroll
    for (int i = 0; i < MT; i++)
#pragma unroll
        for (int j = 0; j < 4; j++)
#pragma unroll
            for (int r = 0; r < 4; r++) acc[i][j][r] = 0.f;

    const int KT = K / 32;

    auto issue_stage = [&](int buf, int kt) {
#pragma unroll
        for (int i = 0; i < CP_IT; i++) {
            int c = tid + i * 256;
            uint32_t sa;
            const __half* gp;
            if (c < A_CHUNK) {
                int tile = c / (BM * 4);
                int rem  = c % (BM * 4);
                int row  = rem >> 2, c16 = rem & 3;
                gp = srcs[tile] + (size_t)row * K + kt * 32 + c16 * 8;
                sa = sbase + buf * STAGE + tile * A_TILE + row * 80 + c16 * 16;
            } else {
                int cc  = c - A_CHUNK;
                int row = cc >> 2, c16 = cc & 3;
                gp = srcs[2] + (size_t)row * K + kt * 32 + c16 * 8;
                sa = sbase + buf * STAGE + 2 * A_TILE + row * 80 + c16 * 16;
            }
            CP_ASYNC16(sa, gp);
        }
        CP_COMMIT();
    };

    const uint32_t aOff = (uint32_t)(wm * (BM / 2) + (lane & 15)) * 80 + ((lane >> 4) & 1) * 16;
    const uint32_t bOff = (uint32_t)(wn * 32 + (lane & 15)) * 80 + ((lane >> 4) & 1) * 16;

    issue_stage(0, 0);

    for (int kt = 0; kt < KT; kt++) {
        const int buf = kt & 1;
        if (kt + 1 < KT) {
            issue_stage(buf ^ 1, kt + 1);
            asm volatile("cp.async.wait_group 1;" ::: "memory");
        } else {
            asm volatile("cp.async.wait_group 0;" ::: "memory");
        }
        __syncthreads();

        const uint32_t stage = sbase + buf * STAGE;
        const uint32_t aAh = stage + aOff;
        const uint32_t aAl = aAh + A_TILE;
        const uint32_t aB  = stage + 2 * A_TILE + bOff;

#pragma unroll
        for (int ks = 0; ks < 2; ks++) {
            const uint32_t ko = ks * 32;
            uint32_t bq[4][2];
#pragma unroll
            for (int np = 0; np < 2; np++)
                LDSM_X4(bq[np*2][0], bq[np*2+1][0], bq[np*2][1], bq[np*2+1][1],
                        aB + np * (16 * 80) + ko);
            uint32_t ah[MT][4], al[MT][4];
#pragma unroll
            for (int mt = 0; mt < MT; mt++) {
                LDSM_X4(ah[mt][0], ah[mt][1], ah[mt][2], ah[mt][3],
                        aAh + mt * (16 * 80) + ko);
                LDSM_X4(al[mt][0], al[mt][1], al[mt][2], al[mt][3],
                        aAl + mt * (16 * 80) + ko);
            }
#pragma unroll
            for (int mt = 0; mt < MT; mt++)
#pragma unroll
                for (int nt = 0; nt < 4; nt++) {
                    MMA_F16(acc[mt][nt], ah[mt], bq[nt]);
                    MMA_F16(acc[mt][nt], al[mt], bq[nt]);
                }
        }
        __syncthreads();
    }

#pragma unroll
    for (int mt = 0; mt < MT; mt++) {
        const int row0 = m0 + wm * (BM / 2) + mt * 16 + g;
#pragma unroll
        for (int nt = 0; nt < 4; nt++) {
            const int col = n0 + wn * 32 + nt * 8 + tig * 2;
            const float b0 = bias[col], b1 = bias[col + 1];
            float2 v0 = make_float2(acc[mt][nt][0] + b0, acc[mt][nt][1] + b1);
            float2 v1 = make_float2(acc[mt][nt][2] + b0, acc[mt][nt][3] + b1);
            *(float2*)&C[(size_t)row0 * N + col]       = v0;
            *(float2*)&C[(size_t)(row0 + 8) * N + col] = v1;
        }
    }
}

// ---------------------------------------------------------------------------
// Persistent-segment HMMA attention with fused rope + fp16 splits.
// grid = (8 segs, 16 heads) = 128 CTAs. 256 threads.  (R8, unchanged)
// ---------------------------------------------------------------------------
#define AQROW   176
#define ASS_LD  268
#define SM_K    0
#define SM_V    45056
#define SM_QH   90112
#define SM_QL   101376
#define SM_SS   112640
#define ATTN_SMEM (112640 + 64 * ASS_LD * 4)

__global__ __launch_bounds__(256, 1)
void attn_mma_kernel(const float* __restrict__ qkv,
                     const float* __restrict__ cosb,
                     const float* __restrict__ sinb,
                     const int* __restrict__ cu,
                     __half* __restrict__ oh,
                     __half* __restrict__ ol) {
    extern __shared__ __align__(16) char sm[];
    const uint32_t sb = smem_to_u32(sm);
    float* sS = (float*)(sm + SM_SS);

    const int tid  = threadIdx.x;
    const int wid  = tid >> 5;
    const int lane = tid & 31;
    const int seg  = blockIdx.x;
    const int head = blockIdx.y;

    const int segStart = cu[seg];
    const int hb = head * HDIM;
    const float scale = rsqrtf((float)HDIM);

    for (int i = tid; i < SEG * 40; i += 256) {
        int r = i / 40, d = i % 40;
        int s = segStart + r;
        float c1 = cosb[s * HDIM + d],      s1 = sinb[s * HDIM + d];
        float c2 = cosb[s * HDIM + d + 40], s2 = sinb[s * HDIM + d + 40];
        size_t gb = (size_t)s * QKV_N + HID + hb + d;
        float k1 = qkv[gb], k2 = qkv[gb + 40];
        __half* kp = (__half*)(sm + SM_K + r * AQROW);
        kp[d]      = __float2half_rn(k1 * c1 - k2 * s1);
        kp[d + 40] = __float2half_rn(k2 * c2 + k1 * s2);
    }
    for (int i = tid; i < SEG * 20; i += 256) {
        int r = i / 20, c = i % 20;
        float4 v = *(const float4*)&qkv[(size_t)(segStart + r) * QKV_N + 2 * HID + hb + c * 4];
        __half2* vp = (__half2*)(sm + SM_V + r * AQROW + c * 8);
        vp[0] = __floats2half2_rn(v.x, v.y);
        vp[1] = __floats2half2_rn(v.z, v.w);
    }

    for (int chunk = 0; chunk < 4; chunk++) {
        const int q0 = segStart + chunk * 64;

        for (int i = tid; i < 64 * 40; i += 256) {
            int r = i / 40, d = i % 40;
            int s = q0 + r;
            float c1 = cosb[s * HDIM + d],      s1 = sinb[s * HDIM + d];
            float c2 = cosb[s * HDIM + d + 40], s2 = sinb[s * HDIM + d + 40];
            size_t gb = (size_t)s * QKV_N + hb + d;
            float q1 = qkv[gb], q2 = qkv[gb + 40];
            float qa = (q1 * c1 - q2 * s1) * scale;
            float qb = (q2 * c2 + q1 * s2) * scale;
            __half* qhp = (__half*)(sm + SM_QH + r * AQROW);
            __half* qlp = (__half*)(sm + SM_QL + r * AQROW);
            __half t;
            t = __float2half_rn(qa); qhp[d]      = t; qlp[d]      = __float2half_rn(qa - __half2float(t));
            t = __float2half_rn(qb); qhp[d + 40] = t; qlp[d + 40] = __float2half_rn(qb - __half2float(t));
        }
        __syncthreads();

        {
            const int wm = wid & 1, wn = wid >> 1;
            float acc[2][8][4];
#pragma unroll
            for (int i = 0; i < 2; i++)
#pragma unroll
                for (int j = 0; j < 8; j++)
#pragma unroll
                    for (int r = 0; r < 4; r++) acc[i][j][r] = 0.f;

            const uint32_t aBase = sb + SM_QH + (uint32_t)(wm * 32 + (lane & 15)) * AQROW
                                   + ((lane >> 4) & 1) * 16;
            const uint32_t bBase = sb + SM_K + (uint32_t)(wn * 64 + (lane & 15)) * AQROW
                                   + ((lane >> 4) & 1) * 16;

#pragma unroll
            for (int ks = 0; ks < 5; ks++) {
                const uint32_t ko = ks * 32;
                uint32_t ah[2][4], al[2][4];
#pragma unroll
                for (int mt = 0; mt < 2; mt++) {
                    LDSM_X4(ah[mt][0], ah[mt][1], ah[mt][2], ah[mt][3],
                            aBase + mt * (16 * AQROW) + ko);
                    LDSM_X4(al[mt][0], al[mt][1], al[mt][2], al[mt][3],
                            aBase + (SM_QL - SM_QH) + mt * (16 * AQROW) + ko);
                }
#pragma unroll
                for (int np = 0; np < 4; np++) {
                    uint32_t bk[2][2];
                    LDSM_X4(bk[0][0], bk[1][0], bk[0][1], bk[1][1],
                            bBase + np * (16 * AQROW) + ko);
#pragma unroll
                    for (int mt = 0; mt < 2; mt++)
#pragma unroll
                        for (int j = 0; j < 2; j++) {
                            MMA_F16(acc[mt][np*2+j], ah[mt], bk[j]);
                            MMA_F16(acc[mt][np*2+j], al[mt], bk[j]);
                        }
                }
            }
#pragma unroll
            for (int mt = 0; mt < 2; mt++) {
                const int r = wm * 32 + mt * 16 + (lane >> 2);
#pragma unroll
                for (int nt = 0; nt < 8; nt++) {
                    const int c = wn * 64 + nt * 8 + 2 * (lane & 3);
                    *(float2*)&sS[r * ASS_LD + c] =
                        make_float2(acc[mt][nt][0], acc[mt][nt][1]);
                    *(float2*)&sS[(r + 8) * ASS_LD + c] =
                        make_float2(acc[mt][nt][2], acc[mt][nt][3]);
                }
            }
        }
        __syncthreads();

        {
            const int r  = tid >> 2;
            const int cl = tid & 3;
            float mx = -1e30f;
#pragma unroll
            for (int j = 0; j < 64; j++)
                mx = fmaxf(mx, sS[r * ASS_LD + cl + 4 * j]);
            mx = fmaxf(mx, __shfl_xor_sync(0xFFFFFFFFu, mx, 1));
            mx = fmaxf(mx, __shfl_xor_sync(0xFFFFFFFFu, mx, 2));
            float sum = 0.f;
#pragma unroll
            for (int j = 0; j < 64; j++) {
                int c = cl + 4 * j;
                float e = __expf(sS[r * ASS_LD + c] - mx);
                sS[r * ASS_LD + c] = e;
                sum += e;
            }
            sum += __shfl_xor_sync(0xFFFFFFFFu, sum, 1);
            sum += __shfl_xor_sync(0xFFFFFFFFu, sum, 2);
            float inv = 1.f / sum;
#pragma unroll
            for (int j = 0; j < 64; j++) sS[r * ASS_LD + cl + 4 * j] *= inv;
        }
        __syncthreads();

        {
            const int wr = wid >> 1, wc = wid & 1;
            float facc[5][4];
#pragma unroll
            for (int i = 0; i < 5; i++)
#pragma unroll
                for (int r = 0; r < 4; r++) facc[i][r] = 0.f;

            const int pr = wr * 16 + (lane >> 2);
            const uint32_t vRowOff = (uint32_t)((lane & 7) + ((lane >> 3) & 1) * 8) * AQROW;
            const uint32_t vColHi  = ((lane >> 4) & 1) * 16;

#pragma unroll
            for (int ks = 0; ks < 16; ks++) {
                const int c = ks * 16 + 2 * (lane & 3);
                float2 p00 = *(float2*)&sS[pr * ASS_LD + c];
                float2 p01 = *(float2*)&sS[pr * ASS_LD + c + 8];
                float2 p10 = *(float2*)&sS[(pr + 8) * ASS_LD + c];
                float2 p11 = *(float2*)&sS[(pr + 8) * ASS_LD + c + 8];
                uint32_t pha[4], pla[4];
                split2h(p00, pha[0], pla[0]);
                split2h(p10, pha[1], pla[1]);
                split2h(p01, pha[2], pla[2]);
                split2h(p11, pha[3], pla[3]);

                const uint32_t vk = sb + SM_V + (uint32_t)(ks * 16) * AQROW + vRowOff;

#pragma unroll
                for (int np = 0; np < 2; np++) {
                    const uint32_t co = (uint32_t)(wc * 40 + np * 16) * 2 + vColHi;
                    uint32_t bv[2][2];
                    LDSM_X4T(bv[0][0], bv[0][1], bv[1][0], bv[1][1], vk + co);
#pragma unroll
                    for (int j = 0; j < 2; j++) {
                        MMA_F16(facc[np*2+j], pha, bv[j]);
                        MMA_F16(facc[np*2+j], pla, bv[j]);
                    }
                }
                {
                    const uint32_t co = (uint32_t)(wc * 40 + 32) * 2;
                    uint32_t b4[2];
                    LDSM_X2T(b4[0], b4[1], vk + co);
                    MMA_F16(facc[4], pha, b4);
                    MMA_F16(facc[4], pla, b4);
                }
            }

            const int row0 = q0 + wr * 16 + (lane >> 2);
#pragma unroll
            for (int nt = 0; nt < 5; nt++) {
                const int col = hb + wc * 40 + nt * 8 + 2 * (lane & 3);
                uint32_t h0, l0, h1, l1;
                split2h(make_float2(facc[nt][0], facc[nt][1]), h0, l0);
                split2h(make_float2(facc[nt][2], facc[nt][3]), h1, l1);
                *(uint32_t*)(oh + (size_t)row0 * HID + col)       = h0;
                *(uint32_t*)(ol + (size_t)row0 * HID + col)       = l0;
                *(uint32_t*)(oh + (size_t)(row0 + 8) * HID + col) = h1;
                *(uint32_t*)(ol + (size_t)(row0 + 8) * HID + col) = l1;
            }
        }
        __syncthreads();
    }
}

// ---------------------------------------------------------------------------
extern "C" void kernel_launch(void* const* d_in, const int* in_sizes, int n_in,
                              void* d_out, int out_size) {
    const float* x      = (const float*)d_in[0];
    const float* cosb   = (const float*)d_in[1];
    const float* sinb   = (const float*)d_in[2];
    const float* W_qkv  = (const float*)d_in[3];
    const float* b_qkv  = (const float*)d_in[4];
    const float* W_out  = (const float*)d_in[5];
    const float* b_out  = (const float*)d_in[6];
    const int*   cu     = (const int*)d_in[7];
    float*       outp   = (float*)d_out;

    float* qkv;
    __half *xh, *xl, *ah, *al, *wq, *wo;
    cudaGetSymbolAddress((void**)&qkv, g_qkv);
    cudaGetSymbolAddress((void**)&xh,  g_xh);
    cudaGetSymbolAddress((void**)&xl,  g_xl);
    cudaGetSymbolAddress((void**)&ah,  g_ah);
    cudaGetSymbolAddress((void**)&al,  g_al);
    cudaGetSymbolAddress((void**)&wq,  g_wq);
    cudaGetSymbolAddress((void**)&wo,  g_wo);

    constexpr int SMEM128 = 2 * (2 * 128 * 80 + 128 * 80);   // 61440
    constexpr int SMEM64  = 2 * (2 * 64 * 80 + 128 * 80);    // 40960

    static bool attr_set = false;
    if (!attr_set) {
        cudaFuncSetAttribute(attn_mma_kernel,
                             cudaFuncAttributeMaxDynamicSharedMemorySize, ATTN_SMEM);
        cudaFuncSetAttribute(gemm_f16x2_kernel<128>,
                             cudaFuncAttributeMaxDynamicSharedMemorySize, SMEM128);
        cudaFuncSetAttribute(gemm_f16x2_kernel<64>,
                             cudaFuncAttributeMaxDynamicSharedMemorySize, SMEM64);
        attr_set = true;
    }

    // 0. merged prep (split x, transpose both weights)
    prep_kernel<<<8960, 256>>>(x, W_qkv, W_out, xh, xl, wq, wo);
    // 1. QKV projection (BM=128, grid 480)
    gemm_f16x2_kernel<128><<<dim3(QKV_N / 128, S_LEN / 128), 256, SMEM128>>>(
        S_LEN, QKV_N, HID, xh, xl, wq, b_qkv, qkv);
    // 2. attention (fused rope/splits) -> ah/al
    attn_mma_kernel<<<dim3(NSEG, NHEAD), 256, ATTN_SMEM>>>(
        qkv, cosb, sinb, cu, ah, al);
    // 3. out projection (BM=64, grid 320 -> 2 CTA/SM feeding)
    gemm_f16x2_kernel<64><<<dim3(HID / 128, S_LEN / 64), 256, SMEM64>>>(
        S_LEN, HID, HID, ah, al, wo, b_out, outp);
}